// round 2
// baseline (speedup 1.0000x reference)
#include <cuda_runtime.h>
#include <cstdint>
#include <cstddef>

#define B_   64
#define T_   512
#define DIN  1024
#define DH   2048
#define DOUT 1024
#define M1   (B_ * T_)   // 32768

// Scratch (device globals: allocation-free per harness rules)
__device__ float g_xh[(size_t)M1 * DH];   // 256 MB: precomputed input projection
__device__ float g_h[2][B_ * DH];         // ping-pong hidden state

// Packed fp32x2 FMA (FFMA2) — 2x fp32 FMA rate vs FFMA-3reg on sm_103a
__device__ __forceinline__ float2 ffma2(float2 a, float2 b, float2 c) {
    float2 d;
    asm("fma.rn.f32x2 %0, %1, %2, %3;"
        : "=l"(reinterpret_cast<unsigned long long&>(d))
        : "l"(reinterpret_cast<unsigned long long&>(a)),
          "l"(reinterpret_cast<unsigned long long&>(b)),
          "l"(reinterpret_cast<unsigned long long&>(c)));
    return d;
}

// ---------------------------------------------------------------------------
// Kernel 1: g_xh[M1, DH] = x[M1, DIN] @ W_x2h[DH, DIN]^T + b_x2h
// 128x128 tile, BK=16, 256 threads, 8x8 outputs/thread, f32x2 inner loop.
// ---------------------------------------------------------------------------
__global__ __launch_bounds__(256) void k_xh(const float* __restrict__ A,
                                            const float* __restrict__ W,
                                            const float* __restrict__ bias) {
    __shared__ float As[16][128];
    __shared__ float Bs[16][128];
    const int K  = DIN;
    const int N  = DH;
    const int m0 = blockIdx.y * 128;
    const int n0 = blockIdx.x * 128;
    const int t  = threadIdx.x;
    const int tx = t & 15, ty = t >> 4;

    // acc pairs along M: pair p covers rows {base_p, base_p+1}
    float2 acc[4][8];
#pragma unroll
    for (int p = 0; p < 4; p++)
#pragma unroll
        for (int j = 0; j < 8; j++) acc[p][j] = make_float2(0.f, 0.f);

    const int lrow = t >> 2;   // 0..63
    const int lkq  = t & 3;    // 0..3

    for (int k0 = 0; k0 < K; k0 += 16) {
        // stage global loads in regs (2 float4 per matrix per thread)
        float4 a0 = *(const float4*)(A + (size_t)(m0 + lrow)      * K + k0 + lkq * 4);
        float4 a1 = *(const float4*)(A + (size_t)(m0 + 64 + lrow) * K + k0 + lkq * 4);
        float4 b0 = *(const float4*)(W + (size_t)(n0 + lrow)      * K + k0 + lkq * 4);
        float4 b1 = *(const float4*)(W + (size_t)(n0 + 64 + lrow) * K + k0 + lkq * 4);
        __syncthreads();
        As[lkq*4+0][lrow] = a0.x; As[lkq*4+1][lrow] = a0.y;
        As[lkq*4+2][lrow] = a0.z; As[lkq*4+3][lrow] = a0.w;
        As[lkq*4+0][64+lrow] = a1.x; As[lkq*4+1][64+lrow] = a1.y;
        As[lkq*4+2][64+lrow] = a1.z; As[lkq*4+3][64+lrow] = a1.w;
        Bs[lkq*4+0][lrow] = b0.x; Bs[lkq*4+1][lrow] = b0.y;
        Bs[lkq*4+2][lrow] = b0.z; Bs[lkq*4+3][lrow] = b0.w;
        Bs[lkq*4+0][64+lrow] = b1.x; Bs[lkq*4+1][64+lrow] = b1.y;
        Bs[lkq*4+2][64+lrow] = b1.z; Bs[lkq*4+3][64+lrow] = b1.w;
        __syncthreads();

#pragma unroll
        for (int kk = 0; kk < 16; kk++) {
            float4 av0 = *(const float4*)&As[kk][ty*4];
            float4 av1 = *(const float4*)&As[kk][64 + ty*4];
            float4 bv0 = *(const float4*)&Bs[kk][tx*4];
            float4 bv1 = *(const float4*)&Bs[kk][64 + tx*4];
            float2 ap[4] = { make_float2(av0.x, av0.y), make_float2(av0.z, av0.w),
                             make_float2(av1.x, av1.y), make_float2(av1.z, av1.w) };
            float  bb[8] = { bv0.x, bv0.y, bv0.z, bv0.w, bv1.x, bv1.y, bv1.z, bv1.w };
#pragma unroll
            for (int j = 0; j < 8; j++) {
                float2 b2 = make_float2(bb[j], bb[j]);
#pragma unroll
                for (int p = 0; p < 4; p++)
                    acc[p][j] = ffma2(ap[p], b2, acc[p][j]);
            }
        }
    }

    // epilogue: add bias, store float4 pairs
    float4 bias0 = *(const float4*)(bias + n0 + tx*4);
    float4 bias1 = *(const float4*)(bias + n0 + 64 + tx*4);
    float bv[8] = { bias0.x, bias0.y, bias0.z, bias0.w,
                    bias1.x, bias1.y, bias1.z, bias1.w };
#pragma unroll
    for (int i = 0; i < 8; i++) {
        int lr = (i < 4) ? (ty*4 + i) : (64 + ty*4 + (i - 4));
        int p  = i >> 1;
        float* Cp = g_xh + (size_t)(m0 + lr) * N + n0 + tx*4;
        float4 s0, s1;
        if (i & 1) {
            s0 = make_float4(acc[p][0].y + bv[0], acc[p][1].y + bv[1],
                             acc[p][2].y + bv[2], acc[p][3].y + bv[3]);
            s1 = make_float4(acc[p][4].y + bv[4], acc[p][5].y + bv[5],
                             acc[p][6].y + bv[6], acc[p][7].y + bv[7]);
        } else {
            s0 = make_float4(acc[p][0].x + bv[0], acc[p][1].x + bv[1],
                             acc[p][2].x + bv[2], acc[p][3].x + bv[3]);
            s1 = make_float4(acc[p][4].x + bv[4], acc[p][5].x + bv[5],
                             acc[p][6].x + bv[6], acc[p][7].x + bv[7]);
        }
        *(float4*)Cp        = s0;
        *(float4*)(Cp + 64) = s1;
    }
}

// ---------------------------------------------------------------------------
// Kernel 2: one recurrence step.
// Hout[64, DH] = relu(xh[:, step, :] + Hin @ W_h2h^T)
// 32x32 tile, BK=16, 128 threads, 4x2 outputs/thread, grid (64, 2) = 128 blocks.
// W_h2h (16 MB) stays L2-resident across all 512 steps.
// ---------------------------------------------------------------------------
__global__ __launch_bounds__(128) void k_step(const float* __restrict__ W,
                                              int step, int pin) {
    __shared__ float Hs[16][32];
    __shared__ float Ws[16][32];
    const int K  = DH;
    const int n0 = blockIdx.x * 32;
    const int m0 = blockIdx.y * 32;
    const int t  = threadIdx.x;
    const int nx = t & 15, my = t >> 4;
    const float* __restrict__ Hin  = g_h[pin];
    float* __restrict__       Hout = g_h[pin ^ 1];
    const int lrow = t >> 2;   // 0..31
    const int lkq  = t & 3;

    float2 acc[2][2] = { { make_float2(0.f, 0.f), make_float2(0.f, 0.f) },
                         { make_float2(0.f, 0.f), make_float2(0.f, 0.f) } };

    for (int k0 = 0; k0 < K; k0 += 16) {
        float4 va = *(const float4*)(Hin + (size_t)(m0 + lrow) * K + k0 + lkq * 4);
        float4 vb = *(const float4*)(W   + (size_t)(n0 + lrow) * K + k0 + lkq * 4);
        __syncthreads();
        Hs[lkq*4+0][lrow] = va.x; Hs[lkq*4+1][lrow] = va.y;
        Hs[lkq*4+2][lrow] = va.z; Hs[lkq*4+3][lrow] = va.w;
        Ws[lkq*4+0][lrow] = vb.x; Ws[lkq*4+1][lrow] = vb.y;
        Ws[lkq*4+2][lrow] = vb.z; Ws[lkq*4+3][lrow] = vb.w;
        __syncthreads();

#pragma unroll
        for (int kk = 0; kk < 16; kk++) {
            float4 a = *(const float4*)&Hs[kk][my*4];
            float2 b = *(const float2*)&Ws[kk][nx*2];
            float2 ap0 = make_float2(a.x, a.y), ap1 = make_float2(a.z, a.w);
            float2 b0  = make_float2(b.x, b.x), b1  = make_float2(b.y, b.y);
            acc[0][0] = ffma2(ap0, b0, acc[0][0]);
            acc[1][0] = ffma2(ap1, b0, acc[1][0]);
            acc[0][1] = ffma2(ap0, b1, acc[0][1]);
            acc[1][1] = ffma2(ap1, b1, acc[1][1]);
        }
    }

    const int c0 = n0 + nx*2;
#pragma unroll
    for (int i = 0; i < 4; i++) {
        int m = m0 + my*4 + i;
        float v0 = (i & 1) ? acc[i>>1][0].y : acc[i>>1][0].x;
        float v1 = (i & 1) ? acc[i>>1][1].y : acc[i>>1][1].x;
        float2 xh2 = *(const float2*)(g_xh + ((size_t)m * T_ + step) * DH + c0);
        float2 o = make_float2(fmaxf(v0 + xh2.x, 0.f), fmaxf(v1 + xh2.y, 0.f));
        *(float2*)(Hout + (size_t)m * DH + c0) = o;
    }
}

// ---------------------------------------------------------------------------
// Kernel 3: y[64, DOUT] = g_h[0] @ W_h2y[DOUT, DH]^T + b_h2y
// ---------------------------------------------------------------------------
__global__ __launch_bounds__(128) void k_out(const float* __restrict__ W,
                                             const float* __restrict__ bias,
                                             float* __restrict__ Y) {
    __shared__ float Hs[16][32];
    __shared__ float Ws[16][32];
    const int K  = DH;
    const int n0 = blockIdx.x * 32;
    const int m0 = blockIdx.y * 32;
    const int t  = threadIdx.x;
    const int nx = t & 15, my = t >> 4;
    const float* __restrict__ Hin = g_h[0];
    const int lrow = t >> 2;
    const int lkq  = t & 3;

    float2 acc[2][2] = { { make_float2(0.f, 0.f), make_float2(0.f, 0.f) },
                         { make_float2(0.f, 0.f), make_float2(0.f, 0.f) } };

    for (int k0 = 0; k0 < K; k0 += 16) {
        float4 va = *(const float4*)(Hin + (size_t)(m0 + lrow) * K + k0 + lkq * 4);
        float4 vb = *(const float4*)(W   + (size_t)(n0 + lrow) * K + k0 + lkq * 4);
        __syncthreads();
        Hs[lkq*4+0][lrow] = va.x; Hs[lkq*4+1][lrow] = va.y;
        Hs[lkq*4+2][lrow] = va.z; Hs[lkq*4+3][lrow] = va.w;
        Ws[lkq*4+0][lrow] = vb.x; Ws[lkq*4+1][lrow] = vb.y;
        Ws[lkq*4+2][lrow] = vb.z; Ws[lkq*4+3][lrow] = vb.w;
        __syncthreads();

#pragma unroll
        for (int kk = 0; kk < 16; kk++) {
            float4 a = *(const float4*)&Hs[kk][my*4];
            float2 b = *(const float2*)&Ws[kk][nx*2];
            float2 ap0 = make_float2(a.x, a.y), ap1 = make_float2(a.z, a.w);
            float2 b0  = make_float2(b.x, b.x), b1  = make_float2(b.y, b.y);
            acc[0][0] = ffma2(ap0, b0, acc[0][0]);
            acc[1][0] = ffma2(ap1, b0, acc[1][0]);
            acc[0][1] = ffma2(ap0, b1, acc[0][1]);
            acc[1][1] = ffma2(ap1, b1, acc[1][1]);
        }
    }

    const int c0 = n0 + nx*2;
    float2 bb = *(const float2*)(bias + c0);
#pragma unroll
    for (int i = 0; i < 4; i++) {
        int m = m0 + my*4 + i;
        float v0 = (i & 1) ? acc[i>>1][0].y : acc[i>>1][0].x;
        float v1 = (i & 1) ? acc[i>>1][1].y : acc[i>>1][1].x;
        float2 o = make_float2(v0 + bb.x, v1 + bb.y);
        *(float2*)(Y + (size_t)m * DOUT + c0) = o;
    }
}

__global__ void k_zero() {
    g_h[0][blockIdx.x * 256 + threadIdx.x] = 0.f;
}

// ---------------------------------------------------------------------------
extern "C" void kernel_launch(void* const* d_in, const int* in_sizes, int n_in,
                              void* d_out, int out_size) {
    (void)in_sizes; (void)n_in; (void)out_size;
    const float* x     = (const float*)d_in[0];
    const float* W_x2h = (const float*)d_in[1];
    const float* b_x2h = (const float*)d_in[2];
    const float* W_h2h = (const float*)d_in[3];
    const float* W_h2y = (const float*)d_in[4];
    const float* b_h2y = (const float*)d_in[5];
    float* y = (float*)d_out;

    // 1) input projection for all timesteps: one big GEMM
    k_xh<<<dim3(DH / 128, M1 / 128), 256>>>(x, W_x2h, b_x2h);

    // 2) h0 = 0, then 512 recurrence steps (ping-pong g_h buffers)
    k_zero<<<(B_ * DH) / 256, 256>>>();
    for (int s = 0; s < T_; s++)
        k_step<<<dim3(DH / 32, B_ / 32), 128>>>(W_h2h, s, s & 1);

    // 3) output projection (final h lives in g_h[0] after 512 steps)
    k_out<<<dim3(DOUT / 32, B_ / 32), 128>>>(W_h2y, b_h2y, y);
}

// round 3
// speedup vs baseline: 2.4403x; 2.4403x over previous
#include <cuda_runtime.h>
#include <cstdint>
#include <cstddef>

#define B_   64
#define T_   512
#define DIN  1024
#define DH   2048
#define DOUT 1024
#define M1   (B_ * T_)   // 32768

// Recurrence persistent-kernel config
#define NBLK   128      // persistent blocks (<=148 SMs -> co-residency guaranteed)
#define NTHR   128      // 4 warps
#define NTILES 32       // N tiles of 64 cols
#define KSPLIT 4        // K split chunks
#define KC     (DH / KSPLIT)   // 512
#define KIN    32       // inner smem K chunk
#define LDT    36       // padded smem row stride (conflict-free: bank = (4m+k)%32)

// ---------------------------------------------------------------------------
// Device globals (allocation-free scratch)
// ---------------------------------------------------------------------------
__device__ float    g_xh[(size_t)M1 * DH];     // 256 MB input projection
__device__ float    g_h[B_ * DH];              // final hidden state (fp32)
__device__ unsigned g_Whi[(size_t)DH * DH];    // tf32 split of W_h2h
__device__ unsigned g_Wlo[(size_t)DH * DH];
__device__ unsigned g_hhi[B_ * DH];            // tf32 split of current h
__device__ unsigned g_hlo[B_ * DH];
__device__ float    g_acc[2][B_ * DH];         // ping-pong pre-activation accumulators
__device__ unsigned g_bar_count;
__device__ unsigned g_bar_phase;

// Packed fp32x2 FMA for the fp32 kernels
__device__ __forceinline__ float2 ffma2(float2 a, float2 b, float2 c) {
    float2 d;
    asm("fma.rn.f32x2 %0, %1, %2, %3;"
        : "=l"(reinterpret_cast<unsigned long long&>(d))
        : "l"(reinterpret_cast<unsigned long long&>(a)),
          "l"(reinterpret_cast<unsigned long long&>(b)),
          "l"(reinterpret_cast<unsigned long long&>(c)));
    return d;
}

__device__ __forceinline__ unsigned f2tf32(float x) {
    unsigned r;
    asm("cvt.rna.tf32.f32 %0, %1;" : "=r"(r) : "f"(x));
    return r;
}

__device__ __forceinline__ void mma_tf32(float* c, const unsigned* a, const unsigned* b) {
    asm volatile(
        "mma.sync.aligned.m16n8k8.row.col.f32.tf32.tf32.f32 "
        "{%0,%1,%2,%3}, {%4,%5,%6,%7}, {%8,%9}, {%0,%1,%2,%3};"
        : "+f"(c[0]), "+f"(c[1]), "+f"(c[2]), "+f"(c[3])
        : "r"(a[0]), "r"(a[1]), "r"(a[2]), "r"(a[3]),
          "r"(b[0]), "r"(b[1]));
}

// ---------------------------------------------------------------------------
// Kernel 1: g_xh = x @ W_x2h^T + b_x2h  (fp32, 128x128 tile, FFMA2)
// ---------------------------------------------------------------------------
__global__ __launch_bounds__(256) void k_xh(const float* __restrict__ A,
                                            const float* __restrict__ W,
                                            const float* __restrict__ bias) {
    __shared__ float As[16][128];
    __shared__ float Bs[16][128];
    const int K  = DIN;
    const int N  = DH;
    const int m0 = blockIdx.y * 128;
    const int n0 = blockIdx.x * 128;
    const int t  = threadIdx.x;
    const int tx = t & 15, ty = t >> 4;

    float2 acc[4][8];
#pragma unroll
    for (int p = 0; p < 4; p++)
#pragma unroll
        for (int j = 0; j < 8; j++) acc[p][j] = make_float2(0.f, 0.f);

    const int lrow = t >> 2;
    const int lkq  = t & 3;

    for (int k0 = 0; k0 < K; k0 += 16) {
        float4 a0 = *(const float4*)(A + (size_t)(m0 + lrow)      * K + k0 + lkq * 4);
        float4 a1 = *(const float4*)(A + (size_t)(m0 + 64 + lrow) * K + k0 + lkq * 4);
        float4 b0 = *(const float4*)(W + (size_t)(n0 + lrow)      * K + k0 + lkq * 4);
        float4 b1 = *(const float4*)(W + (size_t)(n0 + 64 + lrow) * K + k0 + lkq * 4);
        __syncthreads();
        As[lkq*4+0][lrow] = a0.x; As[lkq*4+1][lrow] = a0.y;
        As[lkq*4+2][lrow] = a0.z; As[lkq*4+3][lrow] = a0.w;
        As[lkq*4+0][64+lrow] = a1.x; As[lkq*4+1][64+lrow] = a1.y;
        As[lkq*4+2][64+lrow] = a1.z; As[lkq*4+3][64+lrow] = a1.w;
        Bs[lkq*4+0][lrow] = b0.x; Bs[lkq*4+1][lrow] = b0.y;
        Bs[lkq*4+2][lrow] = b0.z; Bs[lkq*4+3][lrow] = b0.w;
        Bs[lkq*4+0][64+lrow] = b1.x; Bs[lkq*4+1][64+lrow] = b1.y;
        Bs[lkq*4+2][64+lrow] = b1.z; Bs[lkq*4+3][64+lrow] = b1.w;
        __syncthreads();

#pragma unroll
        for (int kk = 0; kk < 16; kk++) {
            float4 av0 = *(const float4*)&As[kk][ty*4];
            float4 av1 = *(const float4*)&As[kk][64 + ty*4];
            float4 bv0 = *(const float4*)&Bs[kk][tx*4];
            float4 bv1 = *(const float4*)&Bs[kk][64 + tx*4];
            float2 ap[4] = { make_float2(av0.x, av0.y), make_float2(av0.z, av0.w),
                             make_float2(av1.x, av1.y), make_float2(av1.z, av1.w) };
            float  bb[8] = { bv0.x, bv0.y, bv0.z, bv0.w, bv1.x, bv1.y, bv1.z, bv1.w };
#pragma unroll
            for (int j = 0; j < 8; j++) {
                float2 b2 = make_float2(bb[j], bb[j]);
#pragma unroll
                for (int p = 0; p < 4; p++)
                    acc[p][j] = ffma2(ap[p], b2, acc[p][j]);
            }
        }
    }

    float4 bias0 = *(const float4*)(bias + n0 + tx*4);
    float4 bias1 = *(const float4*)(bias + n0 + 64 + tx*4);
    float bv[8] = { bias0.x, bias0.y, bias0.z, bias0.w,
                    bias1.x, bias1.y, bias1.z, bias1.w };
#pragma unroll
    for (int i = 0; i < 8; i++) {
        int lr = (i < 4) ? (ty*4 + i) : (64 + ty*4 + (i - 4));
        int p  = i >> 1;
        float* Cp = g_xh + (size_t)(m0 + lr) * N + n0 + tx*4;
        float4 s0, s1;
        if (i & 1) {
            s0 = make_float4(acc[p][0].y + bv[0], acc[p][1].y + bv[1],
                             acc[p][2].y + bv[2], acc[p][3].y + bv[3]);
            s1 = make_float4(acc[p][4].y + bv[4], acc[p][5].y + bv[5],
                             acc[p][6].y + bv[6], acc[p][7].y + bv[7]);
        } else {
            s0 = make_float4(acc[p][0].x + bv[0], acc[p][1].x + bv[1],
                             acc[p][2].x + bv[2], acc[p][3].x + bv[3]);
            s1 = make_float4(acc[p][4].x + bv[4], acc[p][5].x + bv[5],
                             acc[p][6].x + bv[6], acc[p][7].x + bv[7]);
        }
        *(float4*)Cp        = s0;
        *(float4*)(Cp + 64) = s1;
    }
}

// ---------------------------------------------------------------------------
// Kernel: split W_h2h into tf32 hi/lo
// ---------------------------------------------------------------------------
__global__ void k_splitw(const float* __restrict__ W) {
    size_t i = (size_t)blockIdx.x * 256 + threadIdx.x;
    float w = W[i];
    unsigned hi = f2tf32(w);
    g_Whi[i] = hi;
    g_Wlo[i] = f2tf32(w - __uint_as_float(hi));
}

// ---------------------------------------------------------------------------
// Persistent recurrence kernel: 512 steps, tf32x3 MMA, software grid barrier
// Block b: ntile = b%32 (64 cols), kchunk = b/32 (512 K). Epilogue: block b
// owns columns [b*16, b*16+16) of the 64x2048 state.
// ---------------------------------------------------------------------------
__global__ __launch_bounds__(NTHR, 1) void k_recur() {
    __shared__ unsigned sAh[64 * LDT];
    __shared__ unsigned sAl[64 * LDT];
    __shared__ unsigned sBh[64 * LDT];
    __shared__ unsigned sBl[64 * LDT];

    const int tid  = threadIdx.x;
    const int b    = blockIdx.x;
    const int warp = tid >> 5;
    const int lane = tid & 31;
    const int lg   = lane >> 2;   // group id (0..7)
    const int lt   = lane & 3;    // thread in group
    const int ntile  = b & (NTILES - 1);
    const int kchunk = b >> 5;
    const int n0  = ntile * 64;
    const int kc0 = kchunk * KC;
    const int c0  = b * 16;       // epilogue column slice

    // Replay-safe barrier base
    unsigned bar_base;
    asm volatile("ld.acquire.gpu.global.u32 %0, [%1];"
                 : "=r"(bar_base) : "l"(&g_bar_phase));
    unsigned bar_t = 0;

    auto grid_bar = [&]() {
        __syncthreads();
        __threadfence();
        if (tid == 0) {
            bar_t++;
            unsigned arr = atomicAdd(&g_bar_count, 1);
            if (arr == NBLK - 1) {
                atomicExch(&g_bar_count, 0);
                __threadfence();
                atomicAdd(&g_bar_phase, 1);
            } else {
                unsigned p;
                do {
                    __nanosleep(64);
                    asm volatile("ld.acquire.gpu.global.u32 %0, [%1];"
                                 : "=r"(p) : "l"(&g_bar_phase));
                } while (p - bar_base < bar_t);
            }
        } else if ((tid & 31) == 0) {
            bar_t++;   // keep per-thread copies consistent (only tid 0 used)
        } else {
            bar_t++;
        }
        __syncthreads();
    };

    // Pre-seed acc[0] with xh_0
#pragma unroll
    for (int q = 0; q < 2; q++) {
        int idx = tid * 2 + q;          // 0..255
        int m   = idx >> 2;             // 0..63
        int col = c0 + (idx & 3) * 4;
        float4 s = *(const float4*)&g_xh[((size_t)m * T_) * DH + col];
        *(float4*)&g_acc[0][m * DH + col] = s;
    }
    grid_bar();

    for (int t = 0; t < T_; t++) {
        float* accbuf = g_acc[t & 1];

        if (t > 0) {
            float acc[8][4];
#pragma unroll
            for (int nf = 0; nf < 8; nf++)
#pragma unroll
                for (int i = 0; i < 4; i++) acc[nf][i] = 0.f;

            for (int kci = 0; kci < KC / KIN; kci++) {
                const int kc = kc0 + kci * KIN;
                __syncthreads();
#pragma unroll
                for (int j = 0; j < 4; j++) {
                    int idx = tid + j * NTHR;   // 0..511
                    int row = idx >> 3;
                    int q   = (idx & 7) * 4;
                    *(uint4*)&sAh[row * LDT + q] =
                        *(const uint4*)&g_hhi[row * DH + kc + q];
                    *(uint4*)&sAl[row * LDT + q] =
                        *(const uint4*)&g_hlo[row * DH + kc + q];
                    *(uint4*)&sBh[row * LDT + q] =
                        *(const uint4*)&g_Whi[(size_t)(n0 + row) * DH + kc + q];
                    *(uint4*)&sBl[row * LDT + q] =
                        *(const uint4*)&g_Wlo[(size_t)(n0 + row) * DH + kc + q];
                }
                __syncthreads();

#pragma unroll
                for (int kk = 0; kk < KIN / 8; kk++) {
                    const int ka = kk * 8 + lt;
                    const int r0 = warp * 16 + lg;
                    unsigned ah[4] = { sAh[r0 * LDT + ka],       sAh[(r0 + 8) * LDT + ka],
                                       sAh[r0 * LDT + ka + 4],   sAh[(r0 + 8) * LDT + ka + 4] };
                    unsigned al[4] = { sAl[r0 * LDT + ka],       sAl[(r0 + 8) * LDT + ka],
                                       sAl[r0 * LDT + ka + 4],   sAl[(r0 + 8) * LDT + ka + 4] };
#pragma unroll
                    for (int nf = 0; nf < 8; nf++) {
                        const int nb = (nf * 8 + lg) * LDT + ka;
                        unsigned bh[2] = { sBh[nb], sBh[nb + 4] };
                        unsigned bl[2] = { sBl[nb], sBl[nb + 4] };
                        mma_tf32(acc[nf], ah, bh);   // hi*hi
                        mma_tf32(acc[nf], al, bh);   // lo*hi
                        mma_tf32(acc[nf], ah, bl);   // hi*lo
                    }
                }
            }

            // accumulate partials
            const int r0 = warp * 16 + lg;
#pragma unroll
            for (int nf = 0; nf < 8; nf++) {
                const int cb = n0 + nf * 8 + lt * 2;
                atomicAdd(&accbuf[(size_t)r0 * DH + cb],           acc[nf][0]);
                atomicAdd(&accbuf[(size_t)r0 * DH + cb + 1],       acc[nf][1]);
                atomicAdd(&accbuf[(size_t)(r0 + 8) * DH + cb],     acc[nf][2]);
                atomicAdd(&accbuf[(size_t)(r0 + 8) * DH + cb + 1], acc[nf][3]);
            }
        }

        grid_bar();

        // Epilogue: relu + tf32 re-split + seed next acc
#pragma unroll
        for (int q = 0; q < 2; q++) {
            int idx = tid * 2 + q;
            int m   = idx >> 2;
            int col = c0 + (idx & 3) * 4;
            float4 v = *(const float4*)&accbuf[m * DH + col];
            v.x = fmaxf(v.x, 0.f); v.y = fmaxf(v.y, 0.f);
            v.z = fmaxf(v.z, 0.f); v.w = fmaxf(v.w, 0.f);
            uint4 hh, hl;
            hh.x = f2tf32(v.x); hl.x = f2tf32(v.x - __uint_as_float(hh.x));
            hh.y = f2tf32(v.y); hl.y = f2tf32(v.y - __uint_as_float(hh.y));
            hh.z = f2tf32(v.z); hl.z = f2tf32(v.z - __uint_as_float(hh.z));
            hh.w = f2tf32(v.w); hl.w = f2tf32(v.w - __uint_as_float(hh.w));
            *(uint4*)&g_hhi[m * DH + col] = hh;
            *(uint4*)&g_hlo[m * DH + col] = hl;
            if (t == T_ - 1) {
                *(float4*)&g_h[m * DH + col] = v;
            } else {
                float4 s = *(const float4*)&g_xh[((size_t)m * T_ + t + 1) * DH + col];
                *(float4*)&g_acc[(t + 1) & 1][m * DH + col] = s;
            }
        }

        grid_bar();
    }
}

// ---------------------------------------------------------------------------
// Kernel 3: y = g_h @ W_h2y^T + b_h2y (fp32, small)
// ---------------------------------------------------------------------------
__global__ __launch_bounds__(128) void k_out(const float* __restrict__ W,
                                             const float* __restrict__ bias,
                                             float* __restrict__ Y) {
    __shared__ float Hs[16][32];
    __shared__ float Ws[16][32];
    const int K  = DH;
    const int n0 = blockIdx.x * 32;
    const int m0 = blockIdx.y * 32;
    const int t  = threadIdx.x;
    const int nx = t & 15, my = t >> 4;
    const float* __restrict__ Hin = g_h;
    const int lrow = t >> 2;
    const int lkq  = t & 3;

    float2 acc[2][2] = { { make_float2(0.f, 0.f), make_float2(0.f, 0.f) },
                         { make_float2(0.f, 0.f), make_float2(0.f, 0.f) } };

    for (int k0 = 0; k0 < K; k0 += 16) {
        float4 va = *(const float4*)(Hin + (size_t)(m0 + lrow) * K + k0 + lkq * 4);
        float4 vb = *(const float4*)(W   + (size_t)(n0 + lrow) * K + k0 + lkq * 4);
        __syncthreads();
        Hs[lkq*4+0][lrow] = va.x; Hs[lkq*4+1][lrow] = va.y;
        Hs[lkq*4+2][lrow] = va.z; Hs[lkq*4+3][lrow] = va.w;
        Ws[lkq*4+0][lrow] = vb.x; Ws[lkq*4+1][lrow] = vb.y;
        Ws[lkq*4+2][lrow] = vb.z; Ws[lkq*4+3][lrow] = vb.w;
        __syncthreads();

#pragma unroll
        for (int kk = 0; kk < 16; kk++) {
            float4 a = *(const float4*)&Hs[kk][my*4];
            float2 b = *(const float2*)&Ws[kk][nx*2];
            float2 ap0 = make_float2(a.x, a.y), ap1 = make_float2(a.z, a.w);
            float2 b0  = make_float2(b.x, b.x), b1  = make_float2(b.y, b.y);
            acc[0][0] = ffma2(ap0, b0, acc[0][0]);
            acc[1][0] = ffma2(ap1, b0, acc[1][0]);
            acc[0][1] = ffma2(ap0, b1, acc[0][1]);
            acc[1][1] = ffma2(ap1, b1, acc[1][1]);
        }
    }

    const int c0 = n0 + nx*2;
    float2 bb = *(const float2*)(bias + c0);
#pragma unroll
    for (int i = 0; i < 4; i++) {
        int m = m0 + my*4 + i;
        float v0 = (i & 1) ? acc[i>>1][0].y : acc[i>>1][0].x;
        float v1 = (i & 1) ? acc[i>>1][1].y : acc[i>>1][1].x;
        float2 o = make_float2(v0 + bb.x, v1 + bb.y);
        *(float2*)(Y + (size_t)m * DOUT + c0) = o;
    }
}

// ---------------------------------------------------------------------------
extern "C" void kernel_launch(void* const* d_in, const int* in_sizes, int n_in,
                              void* d_out, int out_size) {
    (void)in_sizes; (void)n_in; (void)out_size;
    const float* x     = (const float*)d_in[0];
    const float* W_x2h = (const float*)d_in[1];
    const float* b_x2h = (const float*)d_in[2];
    const float* W_h2h = (const float*)d_in[3];
    const float* W_h2y = (const float*)d_in[4];
    const float* b_h2y = (const float*)d_in[5];
    float* y = (float*)d_out;

    // 1) input projection (fp32) + W split (tf32 hi/lo)
    k_xh<<<dim3(DH / 128, M1 / 128), 256>>>(x, W_x2h, b_x2h);
    k_splitw<<<(DH * DH) / 256, 256>>>(W_h2h);

    // 2) all 512 recurrence steps in ONE persistent kernel (tf32x3 tensor MMA)
    k_recur<<<NBLK, NTHR>>>();

    // 3) output projection
    k_out<<<dim3(DOUT / 32, B_ / 32), 128>>>(W_h2y, b_h2y, y);
}

// round 4
// speedup vs baseline: 2.8711x; 1.1765x over previous
#include <cuda_runtime.h>
#include <cstdint>
#include <cstddef>

#define B_   64
#define T_   512
#define DIN  1024
#define DH   2048
#define DOUT 1024
#define M1   (B_ * T_)   // 32768

// Recurrence persistent-kernel config: 128 blocks = 16 ntiles x 8 kchunks
#define NBLK    128
#define NTHR    128
#define NTILES  16        // 128 cols each
#define KCHUNKS 8         // 256 K each
#define KBTOT   (DH / 8)  // 256 k8-groups total

// ---------------------------------------------------------------------------
// Device globals (allocation-free scratch)
// ---------------------------------------------------------------------------
__device__ float    g_xh[(size_t)M1 * DH];        // 256 MB input projection
__device__ float    g_h[B_ * DH];                 // final hidden state (fp32)
// W_h2h packed in mma-fragment order: uint4 per (ntile, kb, nfrag, lane) =
// {tf32hi(W[n][k]), tf32hi(W[n][k+4]), tf32lo(W[n][k]), tf32lo(W[n][k+4])}
__device__ uint4    g_Wf[(size_t)DH * DH / 2];    // 32 MB
// h packed in A-fragment order: [kb][mfrag][plane(hi/lo)][lane][reg]
__device__ unsigned g_hf[KBTOT * 4 * 2 * 32 * 4]; // 1 MB
__device__ float    g_part[KCHUNKS][B_][DH];      // split-K partials, 4 MB
__device__ unsigned g_bar_count;
__device__ unsigned g_bar_phase;

__device__ __forceinline__ float2 ffma2(float2 a, float2 b, float2 c) {
    float2 d;
    asm("fma.rn.f32x2 %0, %1, %2, %3;"
        : "=l"(reinterpret_cast<unsigned long long&>(d))
        : "l"(reinterpret_cast<unsigned long long&>(a)),
          "l"(reinterpret_cast<unsigned long long&>(b)),
          "l"(reinterpret_cast<unsigned long long&>(c)));
    return d;
}

__device__ __forceinline__ unsigned f2tf32(float x) {
    unsigned r;
    asm("cvt.rna.tf32.f32 %0, %1;" : "=r"(r) : "f"(x));
    return r;
}

__device__ __forceinline__ void mma_tf32(float* c, const unsigned* a,
                                         unsigned b0, unsigned b1) {
    asm volatile(
        "mma.sync.aligned.m16n8k8.row.col.f32.tf32.tf32.f32 "
        "{%0,%1,%2,%3}, {%4,%5,%6,%7}, {%8,%9}, {%0,%1,%2,%3};"
        : "+f"(c[0]), "+f"(c[1]), "+f"(c[2]), "+f"(c[3])
        : "r"(a[0]), "r"(a[1]), "r"(a[2]), "r"(a[3]), "r"(b0), "r"(b1));
}

// ---------------------------------------------------------------------------
// Kernel 1: g_xh = x @ W_x2h^T + b_x2h  (fp32, 128x128 tile, FFMA2)
// ---------------------------------------------------------------------------
__global__ __launch_bounds__(256) void k_xh(const float* __restrict__ A,
                                            const float* __restrict__ W,
                                            const float* __restrict__ bias) {
    __shared__ float As[16][128];
    __shared__ float Bs[16][128];
    const int K  = DIN;
    const int N  = DH;
    const int m0 = blockIdx.y * 128;
    const int n0 = blockIdx.x * 128;
    const int t  = threadIdx.x;
    const int tx = t & 15, ty = t >> 4;

    float2 acc[4][8];
#pragma unroll
    for (int p = 0; p < 4; p++)
#pragma unroll
        for (int j = 0; j < 8; j++) acc[p][j] = make_float2(0.f, 0.f);

    const int lrow = t >> 2;
    const int lkq  = t & 3;

    for (int k0 = 0; k0 < K; k0 += 16) {
        float4 a0 = *(const float4*)(A + (size_t)(m0 + lrow)      * K + k0 + lkq * 4);
        float4 a1 = *(const float4*)(A + (size_t)(m0 + 64 + lrow) * K + k0 + lkq * 4);
        float4 b0 = *(const float4*)(W + (size_t)(n0 + lrow)      * K + k0 + lkq * 4);
        float4 b1 = *(const float4*)(W + (size_t)(n0 + 64 + lrow) * K + k0 + lkq * 4);
        __syncthreads();
        As[lkq*4+0][lrow] = a0.x; As[lkq*4+1][lrow] = a0.y;
        As[lkq*4+2][lrow] = a0.z; As[lkq*4+3][lrow] = a0.w;
        As[lkq*4+0][64+lrow] = a1.x; As[lkq*4+1][64+lrow] = a1.y;
        As[lkq*4+2][64+lrow] = a1.z; As[lkq*4+3][64+lrow] = a1.w;
        Bs[lkq*4+0][lrow] = b0.x; Bs[lkq*4+1][lrow] = b0.y;
        Bs[lkq*4+2][lrow] = b0.z; Bs[lkq*4+3][lrow] = b0.w;
        Bs[lkq*4+0][64+lrow] = b1.x; Bs[lkq*4+1][64+lrow] = b1.y;
        Bs[lkq*4+2][64+lrow] = b1.z; Bs[lkq*4+3][64+lrow] = b1.w;
        __syncthreads();

#pragma unroll
        for (int kk = 0; kk < 16; kk++) {
            float4 av0 = *(const float4*)&As[kk][ty*4];
            float4 av1 = *(const float4*)&As[kk][64 + ty*4];
            float4 bv0 = *(const float4*)&Bs[kk][tx*4];
            float4 bv1 = *(const float4*)&Bs[kk][64 + tx*4];
            float2 ap[4] = { make_float2(av0.x, av0.y), make_float2(av0.z, av0.w),
                             make_float2(av1.x, av1.y), make_float2(av1.z, av1.w) };
            float  bb[8] = { bv0.x, bv0.y, bv0.z, bv0.w, bv1.x, bv1.y, bv1.z, bv1.w };
#pragma unroll
            for (int j = 0; j < 8; j++) {
                float2 b2 = make_float2(bb[j], bb[j]);
#pragma unroll
                for (int p = 0; p < 4; p++)
                    acc[p][j] = ffma2(ap[p], b2, acc[p][j]);
            }
        }
    }

    float4 bias0 = *(const float4*)(bias + n0 + tx*4);
    float4 bias1 = *(const float4*)(bias + n0 + 64 + tx*4);
    float bv[8] = { bias0.x, bias0.y, bias0.z, bias0.w,
                    bias1.x, bias1.y, bias1.z, bias1.w };
#pragma unroll
    for (int i = 0; i < 8; i++) {
        int lr = (i < 4) ? (ty*4 + i) : (64 + ty*4 + (i - 4));
        int p  = i >> 1;
        float* Cp = g_xh + (size_t)(m0 + lr) * N + n0 + tx*4;
        float4 s0, s1;
        if (i & 1) {
            s0 = make_float4(acc[p][0].y + bv[0], acc[p][1].y + bv[1],
                             acc[p][2].y + bv[2], acc[p][3].y + bv[3]);
            s1 = make_float4(acc[p][4].y + bv[4], acc[p][5].y + bv[5],
                             acc[p][6].y + bv[6], acc[p][7].y + bv[7]);
        } else {
            s0 = make_float4(acc[p][0].x + bv[0], acc[p][1].x + bv[1],
                             acc[p][2].x + bv[2], acc[p][3].x + bv[3]);
            s1 = make_float4(acc[p][4].x + bv[4], acc[p][5].x + bv[5],
                             acc[p][6].x + bv[6], acc[p][7].x + bv[7]);
        }
        *(float4*)Cp        = s0;
        *(float4*)(Cp + 64) = s1;
    }
}

// ---------------------------------------------------------------------------
// Pack W_h2h into tf32 hi/lo fragment-order uint4s.
// ---------------------------------------------------------------------------
__global__ void k_packw(const float* __restrict__ W) {
    size_t u = (size_t)blockIdx.x * 256 + threadIdx.x;   // 0 .. 2M-1
    int lane = (int)(u & 31);
    int nf   = (int)((u >> 5) & 15);
    int kb   = (int)((u >> 9) & 255);
    int nt   = (int)(u >> 17);
    int n = nt * 128 + nf * 8 + (lane >> 2);
    int k = kb * 8 + (lane & 3);
    float w0 = W[(size_t)n * DH + k];
    float w1 = W[(size_t)n * DH + k + 4];
    uint4 v;
    v.x = f2tf32(w0);
    v.y = f2tf32(w1);
    v.z = f2tf32(w0 - __uint_as_float(v.x));
    v.w = f2tf32(w1 - __uint_as_float(v.y));
    g_Wf[u] = v;
}

// ---------------------------------------------------------------------------
// Persistent recurrence kernel. All MMA operands are fragment-order LDG.128
// from L2 — no shared memory in the mainloop. Split-K via partial buffers.
// ---------------------------------------------------------------------------
__global__ __launch_bounds__(NTHR, 1) void k_recur() {
    const int tid  = threadIdx.x;
    const int b    = blockIdx.x;
    const int warp = tid >> 5;
    const int lane = tid & 31;
    const int lg   = lane >> 2;
    const int lt   = lane & 3;
    const int mh   = warp >> 1;          // m-half (0/1): rows mh*32..+31
    const int nh   = warp & 1;           // n-half (0/1): cols nh*64..+63
    const int nt   = b >> 3;             // ntile 0..15
    const int kch  = b & 7;              // kchunk 0..7
    const int n0   = nt * 128;
    const int kb0  = kch * 32;           // first k8-group of this chunk
    const int c0   = b * 16;             // epilogue column slice

    // epilogue thread mapping: thread -> (m, 8-col group)
    const int em   = tid >> 1;           // 0..63
    const int ech  = tid & 1;            // 0..1
    const int ecol = c0 + ech * 8;
    const int ekb  = ecol >> 3;          // constant per thread
    const int emf  = em >> 4;
    const int elane = (em & 7) << 2;
    const int ereg0 = (em >> 3) & 1;
    unsigned* hf_hi = g_hf + ((size_t)(ekb * 4 + emf) * 2 + 0) * 128;
    unsigned* hf_lo = g_hf + ((size_t)(ekb * 4 + emf) * 2 + 1) * 128;

    // replay-safe grid barrier
    unsigned bar_base;
    asm volatile("ld.acquire.gpu.global.u32 %0, [%1];"
                 : "=r"(bar_base) : "l"(&g_bar_phase));
    unsigned bar_t = 0;

    auto grid_bar = [&]() {
        bar_t++;
        __syncthreads();
        __threadfence();
        if (tid == 0) {
            unsigned arr = atomicAdd(&g_bar_count, 1);
            if (arr == NBLK - 1) {
                atomicExch(&g_bar_count, 0);
                __threadfence();
                atomicAdd(&g_bar_phase, 1);
            } else {
                unsigned p;
                do {
                    __nanosleep(32);
                    asm volatile("ld.acquire.gpu.global.u32 %0, [%1];"
                                 : "=r"(p) : "l"(&g_bar_phase));
                } while (p - bar_base < bar_t);
            }
        }
        __syncthreads();
    };

    // init: h_1 = relu(xh[:, 0, :])
    {
        const float* xp = &g_xh[((size_t)em * T_) * DH + ecol];
        float4 x0 = __ldcg((const float4*)xp);
        float4 x1 = __ldcg((const float4*)(xp + 4));
        float v[8] = { x0.x, x0.y, x0.z, x0.w, x1.x, x1.y, x1.z, x1.w };
#pragma unroll
        for (int j = 0; j < 8; j++) {
            float vj = fmaxf(v[j], 0.f);
            unsigned hi = f2tf32(vj);
            unsigned lo = f2tf32(vj - __uint_as_float(hi));
            int off = (elane + (j & 3)) * 4 + ereg0 + 2 * (j >> 2);
            hf_hi[off] = hi;
            hf_lo[off] = lo;
        }
    }
    grid_bar();

    for (int s = 2; s <= T_; s++) {
        // ---- MMA phase: acc = h_{s-1}[:, kchunk] @ W[ntile, kchunk]^T ----
        float acc[2][8][4];
#pragma unroll
        for (int mi = 0; mi < 2; mi++)
#pragma unroll
            for (int nf = 0; nf < 8; nf++)
#pragma unroll
                for (int i = 0; i < 4; i++) acc[mi][nf][i] = 0.f;

#pragma unroll 2
        for (int kbl = 0; kbl < 32; kbl++) {
            const int kb = kb0 + kbl;
            const uint4* abase =
                (const uint4*)g_hf + (size_t)(kb * 4 + mh * 2) * 2 * 32;
            uint4 a0h = __ldcg(abase + lane);          // mfrag 0, hi
            uint4 a0l = __ldcg(abase + 32 + lane);     // mfrag 0, lo
            uint4 a1h = __ldcg(abase + 64 + lane);     // mfrag 1, hi
            uint4 a1l = __ldcg(abase + 96 + lane);     // mfrag 1, lo
            const uint4* wbase =
                g_Wf + ((size_t)(nt * 256 + kb) * 16 + nh * 8) * 32;
            uint4 w[8];
#pragma unroll
            for (int nf = 0; nf < 8; nf++) w[nf] = __ldg(wbase + nf * 32 + lane);

            unsigned A0h[4] = { a0h.x, a0h.y, a0h.z, a0h.w };
            unsigned A0l[4] = { a0l.x, a0l.y, a0l.z, a0l.w };
            unsigned A1h[4] = { a1h.x, a1h.y, a1h.z, a1h.w };
            unsigned A1l[4] = { a1l.x, a1l.y, a1l.z, a1l.w };
#pragma unroll
            for (int nf = 0; nf < 8; nf++) {
                mma_tf32(acc[0][nf], A0h, w[nf].x, w[nf].y);  // hi*hi
                mma_tf32(acc[0][nf], A0l, w[nf].x, w[nf].y);  // lo*hi
                mma_tf32(acc[0][nf], A0h, w[nf].z, w[nf].w);  // hi*lo
                mma_tf32(acc[1][nf], A1h, w[nf].x, w[nf].y);
                mma_tf32(acc[1][nf], A1l, w[nf].x, w[nf].y);
                mma_tf32(acc[1][nf], A1h, w[nf].z, w[nf].w);
            }
        }

        // write split-K partials
        {
            float* pb = &g_part[kch][0][0];
            const int colb = n0 + nh * 64 + lt * 2;
#pragma unroll
            for (int mi = 0; mi < 2; mi++) {
                const int r = mh * 32 + mi * 16 + lg;
#pragma unroll
                for (int nf = 0; nf < 8; nf++) {
                    const int c = colb + nf * 8;
                    *(float2*)&pb[(size_t)r * DH + c] =
                        make_float2(acc[mi][nf][0], acc[mi][nf][1]);
                    *(float2*)&pb[(size_t)(r + 8) * DH + c] =
                        make_float2(acc[mi][nf][2], acc[mi][nf][3]);
                }
            }
        }
        grid_bar();

        // ---- epilogue: h_s = relu(xh_{s-1} + sum partials) ----
        {
            const float* xp = &g_xh[((size_t)em * T_ + (s - 1)) * DH + ecol];
            float4 x0 = __ldcg((const float4*)xp);
            float4 x1 = __ldcg((const float4*)(xp + 4));
            float v[8] = { x0.x, x0.y, x0.z, x0.w, x1.x, x1.y, x1.z, x1.w };
#pragma unroll
            for (int kc = 0; kc < KCHUNKS; kc++) {
                const float* pp = &g_part[kc][em][ecol];
                float4 p0 = __ldcg((const float4*)pp);
                float4 p1 = __ldcg((const float4*)(pp + 4));
                v[0] += p0.x; v[1] += p0.y; v[2] += p0.z; v[3] += p0.w;
                v[4] += p1.x; v[5] += p1.y; v[6] += p1.z; v[7] += p1.w;
            }
#pragma unroll
            for (int j = 0; j < 8; j++) {
                float vj = fmaxf(v[j], 0.f);
                unsigned hi = f2tf32(vj);
                unsigned lo = f2tf32(vj - __uint_as_float(hi));
                int off = (elane + (j & 3)) * 4 + ereg0 + 2 * (j >> 2);
                hf_hi[off] = hi;
                hf_lo[off] = lo;
                if (s == T_) g_h[(size_t)em * DH + ecol + j] = vj;
            }
        }
        grid_bar();
    }
}

// ---------------------------------------------------------------------------
// Kernel 3: y = g_h @ W_h2y^T + b_h2y (fp32, small)
// ---------------------------------------------------------------------------
__global__ __launch_bounds__(128) void k_out(const float* __restrict__ W,
                                             const float* __restrict__ bias,
                                             float* __restrict__ Y) {
    __shared__ float Hs[16][32];
    __shared__ float Ws[16][32];
    const int K  = DH;
    const int n0 = blockIdx.x * 32;
    const int m0 = blockIdx.y * 32;
    const int t  = threadIdx.x;
    const int nx = t & 15, my = t >> 4;
    const float* __restrict__ Hin = g_h;
    const int lrow = t >> 2;
    const int lkq  = t & 3;

    float2 acc[2][2] = { { make_float2(0.f, 0.f), make_float2(0.f, 0.f) },
                         { make_float2(0.f, 0.f), make_float2(0.f, 0.f) } };

    for (int k0 = 0; k0 < K; k0 += 16) {
        float4 va = *(const float4*)(Hin + (size_t)(m0 + lrow) * K + k0 + lkq * 4);
        float4 vb = *(const float4*)(W   + (size_t)(n0 + lrow) * K + k0 + lkq * 4);
        __syncthreads();
        Hs[lkq*4+0][lrow] = va.x; Hs[lkq*4+1][lrow] = va.y;
        Hs[lkq*4+2][lrow] = va.z; Hs[lkq*4+3][lrow] = va.w;
        Ws[lkq*4+0][lrow] = vb.x; Ws[lkq*4+1][lrow] = vb.y;
        Ws[lkq*4+2][lrow] = vb.z; Ws[lkq*4+3][lrow] = vb.w;
        __syncthreads();

#pragma unroll
        for (int kk = 0; kk < 16; kk++) {
            float4 a = *(const float4*)&Hs[kk][my*4];
            float2 bq = *(const float2*)&Ws[kk][nx*2];
            float2 ap0 = make_float2(a.x, a.y), ap1 = make_float2(a.z, a.w);
            float2 b0  = make_float2(bq.x, bq.x), b1  = make_float2(bq.y, bq.y);
            acc[0][0] = ffma2(ap0, b0, acc[0][0]);
            acc[1][0] = ffma2(ap1, b0, acc[1][0]);
            acc[0][1] = ffma2(ap0, b1, acc[0][1]);
            acc[1][1] = ffma2(ap1, b1, acc[1][1]);
        }
    }

    const int c0 = n0 + nx*2;
    float2 bb = *(const float2*)(bias + c0);
#pragma unroll
    for (int i = 0; i < 4; i++) {
        int m = m0 + my*4 + i;
        float v0 = (i & 1) ? acc[i>>1][0].y : acc[i>>1][0].x;
        float v1 = (i & 1) ? acc[i>>1][1].y : acc[i>>1][1].x;
        float2 o = make_float2(v0 + bb.x, v1 + bb.y);
        *(float2*)(Y + (size_t)m * DOUT + c0) = o;
    }
}

// ---------------------------------------------------------------------------
extern "C" void kernel_launch(void* const* d_in, const int* in_sizes, int n_in,
                              void* d_out, int out_size) {
    (void)in_sizes; (void)n_in; (void)out_size;
    const float* x     = (const float*)d_in[0];
    const float* W_x2h = (const float*)d_in[1];
    const float* b_x2h = (const float*)d_in[2];
    const float* W_h2h = (const float*)d_in[3];
    const float* W_h2y = (const float*)d_in[4];
    const float* b_h2y = (const float*)d_in[5];
    float* y = (float*)d_out;

    // 1) input projection (fp32) + W fragment pack (tf32 hi/lo)
    k_xh<<<dim3(DH / 128, M1 / 128), 256>>>(x, W_x2h, b_x2h);
    k_packw<<<(DH * DH / 2) / 256, 256>>>(W_h2h);

    // 2) all 512 recurrence steps in ONE persistent kernel (tf32x3 MMA,
    //    fragment-order L2-direct operands, split-K partial buffers)
    k_recur<<<NBLK, NTHR>>>();

    // 3) output projection
    k_out<<<dim3(DOUT / 32, B_ / 32), 128>>>(W_h2y, b_h2y, y);
}

// round 5
// speedup vs baseline: 4.6719x; 1.6272x over previous
#include <cuda_runtime.h>
#include <cuda_bf16.h>
#include <cstdint>
#include <cstddef>

#define B_   64
#define T_   512
#define DIN  1024
#define DH   2048
#define DOUT 1024
#define M1   (B_ * T_)   // 32768

// Recurrence persistent kernel: 128 blocks = 16 ntiles(128 col) x 8 kchunks(256 K)
#define NBLK    128
#define NTHR    256      // 8 warps: (kh, mh, nh)
#define KGG     128      // k16-groups over DH
#define WTILE_U4 8192    // W tile uint4s per block (128KB)

// ---------------------------------------------------------------------------
// Device globals (allocation-free scratch)
// ---------------------------------------------------------------------------
__device__ float    g_xh[(size_t)M1 * DH];        // 256 MB input projection (fp32)
__device__ float    g_h[B_ * DH];                 // final hidden state (fp32)
// W_h2h bf16 hi/lo packed in m16n8k16 B-fragment order, per block tile:
// uint4 {b0_hi, b1_hi, b0_lo, b1_lo} per (block, kg, nfl, lane)
__device__ uint4    g_Wf[(size_t)NBLK * WTILE_U4];   // 16 MB
// h bf16 hi/lo packed in A-fragment order:
// uint4 {a0,a1,a2,a3} per (kgg, mf, plane, lane)
__device__ uint4    g_hf[KGG * 4 * 2 * 32];          // 512 KB
__device__ float    g_part[16][B_][DH];              // split-K partials, 8 MB
__device__ unsigned g_bar_count;
__device__ unsigned g_bar_phase;

__device__ __forceinline__ float2 ffma2(float2 a, float2 b, float2 c) {
    float2 d;
    asm("fma.rn.f32x2 %0, %1, %2, %3;"
        : "=l"(reinterpret_cast<unsigned long long&>(d))
        : "l"(reinterpret_cast<unsigned long long&>(a)),
          "l"(reinterpret_cast<unsigned long long&>(b)),
          "l"(reinterpret_cast<unsigned long long&>(c)));
    return d;
}

// split (v0, v1) into bf16 hi plane + bf16 lo (residual) plane, packed bf16x2
__device__ __forceinline__ void split2(float v0, float v1,
                                       unsigned& hi, unsigned& lo) {
    __nv_bfloat162 h2 = __floats2bfloat162_rn(v0, v1);
    float2 hf = __bfloat1622float2(h2);
    __nv_bfloat162 l2 = __floats2bfloat162_rn(v0 - hf.x, v1 - hf.y);
    hi = *reinterpret_cast<unsigned*>(&h2);
    lo = *reinterpret_cast<unsigned*>(&l2);
}

__device__ __forceinline__ void mma_bf16(float* c, const uint4& a,
                                         unsigned b0, unsigned b1) {
    asm volatile(
        "mma.sync.aligned.m16n8k16.row.col.f32.bf16.bf16.f32 "
        "{%0,%1,%2,%3}, {%4,%5,%6,%7}, {%8,%9}, {%0,%1,%2,%3};"
        : "+f"(c[0]), "+f"(c[1]), "+f"(c[2]), "+f"(c[3])
        : "r"(a.x), "r"(a.y), "r"(a.z), "r"(a.w), "r"(b0), "r"(b1));
}

// ---------------------------------------------------------------------------
// Kernel 1: g_xh = x @ W_x2h^T + b_x2h  (fp32, 128x128 tile, FFMA2) — unchanged
// ---------------------------------------------------------------------------
__global__ __launch_bounds__(256) void k_xh(const float* __restrict__ A,
                                            const float* __restrict__ W,
                                            const float* __restrict__ bias) {
    __shared__ float As[16][128];
    __shared__ float Bs[16][128];
    const int K  = DIN;
    const int N  = DH;
    const int m0 = blockIdx.y * 128;
    const int n0 = blockIdx.x * 128;
    const int t  = threadIdx.x;
    const int tx = t & 15, ty = t >> 4;

    float2 acc[4][8];
#pragma unroll
    for (int p = 0; p < 4; p++)
#pragma unroll
        for (int j = 0; j < 8; j++) acc[p][j] = make_float2(0.f, 0.f);

    const int lrow = t >> 2;
    const int lkq  = t & 3;

    for (int k0 = 0; k0 < K; k0 += 16) {
        float4 a0 = *(const float4*)(A + (size_t)(m0 + lrow)      * K + k0 + lkq * 4);
        float4 a1 = *(const float4*)(A + (size_t)(m0 + 64 + lrow) * K + k0 + lkq * 4);
        float4 b0 = *(const float4*)(W + (size_t)(n0 + lrow)      * K + k0 + lkq * 4);
        float4 b1 = *(const float4*)(W + (size_t)(n0 + 64 + lrow) * K + k0 + lkq * 4);
        __syncthreads();
        As[lkq*4+0][lrow] = a0.x; As[lkq*4+1][lrow] = a0.y;
        As[lkq*4+2][lrow] = a0.z; As[lkq*4+3][lrow] = a0.w;
        As[lkq*4+0][64+lrow] = a1.x; As[lkq*4+1][64+lrow] = a1.y;
        As[lkq*4+2][64+lrow] = a1.z; As[lkq*4+3][64+lrow] = a1.w;
        Bs[lkq*4+0][lrow] = b0.x; Bs[lkq*4+1][lrow] = b0.y;
        Bs[lkq*4+2][lrow] = b0.z; Bs[lkq*4+3][lrow] = b0.w;
        Bs[lkq*4+0][64+lrow] = b1.x; Bs[lkq*4+1][64+lrow] = b1.y;
        Bs[lkq*4+2][64+lrow] = b1.z; Bs[lkq*4+3][64+lrow] = b1.w;
        __syncthreads();

#pragma unroll
        for (int kk = 0; kk < 16; kk++) {
            float4 av0 = *(const float4*)&As[kk][ty*4];
            float4 av1 = *(const float4*)&As[kk][64 + ty*4];
            float4 bv0 = *(const float4*)&Bs[kk][tx*4];
            float4 bv1 = *(const float4*)&Bs[kk][64 + tx*4];
            float2 ap[4] = { make_float2(av0.x, av0.y), make_float2(av0.z, av0.w),
                             make_float2(av1.x, av1.y), make_float2(av1.z, av1.w) };
            float  bb[8] = { bv0.x, bv0.y, bv0.z, bv0.w, bv1.x, bv1.y, bv1.z, bv1.w };
#pragma unroll
            for (int j = 0; j < 8; j++) {
                float2 b2 = make_float2(bb[j], bb[j]);
#pragma unroll
                for (int p = 0; p < 4; p++)
                    acc[p][j] = ffma2(ap[p], b2, acc[p][j]);
            }
        }
    }

    float4 bias0 = *(const float4*)(bias + n0 + tx*4);
    float4 bias1 = *(const float4*)(bias + n0 + 64 + tx*4);
    float bv[8] = { bias0.x, bias0.y, bias0.z, bias0.w,
                    bias1.x, bias1.y, bias1.z, bias1.w };
#pragma unroll
    for (int i = 0; i < 8; i++) {
        int lr = (i < 4) ? (ty*4 + i) : (64 + ty*4 + (i - 4));
        int p  = i >> 1;
        float* Cp = g_xh + (size_t)(m0 + lr) * N + n0 + tx*4;
        float4 s0, s1;
        if (i & 1) {
            s0 = make_float4(acc[p][0].y + bv[0], acc[p][1].y + bv[1],
                             acc[p][2].y + bv[2], acc[p][3].y + bv[3]);
            s1 = make_float4(acc[p][4].y + bv[4], acc[p][5].y + bv[5],
                             acc[p][6].y + bv[6], acc[p][7].y + bv[7]);
        } else {
            s0 = make_float4(acc[p][0].x + bv[0], acc[p][1].x + bv[1],
                             acc[p][2].x + bv[2], acc[p][3].x + bv[3]);
            s1 = make_float4(acc[p][4].x + bv[4], acc[p][5].x + bv[5],
                             acc[p][6].x + bv[6], acc[p][7].x + bv[7]);
        }
        *(float4*)Cp        = s0;
        *(float4*)(Cp + 64) = s1;
    }
}

// ---------------------------------------------------------------------------
// Pack W_h2h into bf16 hi/lo B-fragment order (per-block 128KB tiles).
// ---------------------------------------------------------------------------
__global__ void k_packw(const float* __restrict__ W) {
    size_t u = (size_t)blockIdx.x * 256 + threadIdx.x;   // 0 .. 1M-1
    int b    = (int)(u >> 13);
    int r    = (int)(u & 8191);
    int kg   = r >> 9;          // 0..15
    int nfl  = (r >> 5) & 15;   // 0..15
    int lane = r & 31;
    int nt = b >> 3, kch = b & 7;
    int n = nt * 128 + nfl * 8 + (lane >> 2);
    int k = kch * 256 + kg * 16 + (lane & 3) * 2;
    const float* row = W + (size_t)n * DH;
    float w0 = row[k],     w1 = row[k + 1];
    float w2 = row[k + 8], w3 = row[k + 9];
    uint4 v;
    unsigned lo01, lo89;
    split2(w0, w1, v.x, lo01);
    split2(w2, w3, v.y, lo89);
    v.z = lo01;
    v.w = lo89;
    g_Wf[u] = v;
}

// ---------------------------------------------------------------------------
// Persistent recurrence kernel: bf16x3 mma.m16n8k16, W tile persistent in SMEM,
// 8 warps (2/SMSP), A fragments L2-direct, 16-way split-K partials.
// ---------------------------------------------------------------------------
__global__ __launch_bounds__(NTHR, 1) void k_recur() {
    extern __shared__ uint4 sW[];   // 8192 uint4 = 128 KB

    const int tid  = threadIdx.x;
    const int b    = blockIdx.x;
    const int warp = tid >> 5;
    const int lane = tid & 31;
    const int kh = warp >> 2;          // k-half (0/1): 128 K each
    const int mh = (warp >> 1) & 1;    // m-half: rows mh*32..+31
    const int nh = warp & 1;           // n-half: cols nh*64..+63
    const int nt  = b >> 3;            // ntile 0..15
    const int kch = b & 7;             // kchunk 0..7
    const int pk  = kch * 2 + kh;      // partial buffer index

    // Load persistent W tile into SMEM (once)
    {
        const uint4* wsrc = g_Wf + (size_t)b * WTILE_U4;
        for (int i = tid; i < WTILE_U4; i += NTHR) sW[i] = __ldg(wsrc + i);
    }

    // replay-safe grid barrier
    unsigned bar_base;
    asm volatile("ld.acquire.gpu.global.u32 %0, [%1];"
                 : "=r"(bar_base) : "l"(&g_bar_phase));
    unsigned bar_t = 0;

    auto grid_bar = [&]() {
        bar_t++;
        __syncthreads();
        __threadfence();
        if (tid == 0) {
            unsigned arr = atomicAdd(&g_bar_count, 1);
            if (arr == NBLK - 1) {
                atomicExch(&g_bar_count, 0);
                __threadfence();
                atomicAdd(&g_bar_phase, 1);
            } else {
                unsigned p;
                do {
                    __nanosleep(32);
                    asm volatile("ld.acquire.gpu.global.u32 %0, [%1];"
                                 : "=r"(p) : "l"(&g_bar_phase));
                } while (p - bar_base < bar_t);
            }
        }
        __syncthreads();
    };

    // Epilogue mapping: block b owns kgg = b (16 h-columns), threads 0..127
    const int elane = tid & 31;
    const int emf   = (tid >> 5) & 3;
    const int er    = emf * 16 + (elane >> 2);       // row (and +8)
    const int ek0   = b * 16 + (elane & 3) * 2;      // col (and +1, +8, +9)
    uint4* hf_hi = g_hf + ((b * 4 + emf) * 2 + 0) * 32 + elane;
    uint4* hf_lo = g_hf + ((b * 4 + emf) * 2 + 1) * 32 + elane;

    auto epilogue = [&](int s) {   // computes h_s from xh_{s-1} (+ partials if s>1)
        if (tid < 128) {
            const float* x0 = &g_xh[((size_t)er * T_ + (s - 1)) * DH + ek0];
            const float* x1 = &g_xh[((size_t)(er + 8) * T_ + (s - 1)) * DH + ek0];
            float2 v00 = __ldg((const float2*)x0);        // (er,   k0..k0+1)
            float2 v01 = __ldg((const float2*)(x0 + 8));  // (er,   k0+8..+9)
            float2 v10 = __ldg((const float2*)x1);        // (er+8, k0..k0+1)
            float2 v11 = __ldg((const float2*)(x1 + 8));  // (er+8, k0+8..+9)
            if (s > 1) {
#pragma unroll
                for (int p = 0; p < 16; p++) {
                    const float* pb = &g_part[p][0][0];
                    const float* p0 = pb + (size_t)er * DH + ek0;
                    const float* p1 = pb + (size_t)(er + 8) * DH + ek0;
                    float2 q;
                    q = __ldcg((const float2*)p0);       v00.x += q.x; v00.y += q.y;
                    q = __ldcg((const float2*)(p0 + 8)); v01.x += q.x; v01.y += q.y;
                    q = __ldcg((const float2*)p1);       v10.x += q.x; v10.y += q.y;
                    q = __ldcg((const float2*)(p1 + 8)); v11.x += q.x; v11.y += q.y;
                }
            }
            v00.x = fmaxf(v00.x, 0.f); v00.y = fmaxf(v00.y, 0.f);
            v01.x = fmaxf(v01.x, 0.f); v01.y = fmaxf(v01.y, 0.f);
            v10.x = fmaxf(v10.x, 0.f); v10.y = fmaxf(v10.y, 0.f);
            v11.x = fmaxf(v11.x, 0.f); v11.y = fmaxf(v11.y, 0.f);
            uint4 hi, lo;
            split2(v00.x, v00.y, hi.x, lo.x);   // a0: (r,   k0,k0+1)
            split2(v10.x, v10.y, hi.y, lo.y);   // a1: (r+8, k0,k0+1)
            split2(v01.x, v01.y, hi.z, lo.z);   // a2: (r,   k0+8,k0+9)
            split2(v11.x, v11.y, hi.w, lo.w);   // a3: (r+8, k0+8,k0+9)
            *hf_hi = hi;
            *hf_lo = lo;
            if (s == T_) {
                *(float2*)&g_h[(size_t)er * DH + ek0]           = v00;
                *(float2*)&g_h[(size_t)er * DH + ek0 + 8]       = v01;
                *(float2*)&g_h[(size_t)(er + 8) * DH + ek0]     = v10;
                *(float2*)&g_h[(size_t)(er + 8) * DH + ek0 + 8] = v11;
            }
        }
    };

    epilogue(1);          // h_1 = relu(xh_0)
    grid_bar();

    const int kggbase = kch * 16 + kh * 8;

    for (int s = 2; s <= T_; s++) {
        // ---- MMA phase: partial[pk] = h_{s-1}[:, kslice] @ W[ntile, kslice]^T
        float acc[2][8][4];
#pragma unroll
        for (int mi = 0; mi < 2; mi++)
#pragma unroll
            for (int nf = 0; nf < 8; nf++)
#pragma unroll
                for (int i = 0; i < 4; i++) acc[mi][nf][i] = 0.f;

        // prefetch kg=0 A fragments
        const uint4* ab0 = g_hf + ((kggbase * 4 + mh * 2) * 2) * 32 + lane;
        uint4 A0h = __ldcg(ab0);
        uint4 A0l = __ldcg(ab0 + 32);
        uint4 A1h = __ldcg(ab0 + 64);
        uint4 A1l = __ldcg(ab0 + 96);

#pragma unroll
        for (int kg = 0; kg < 8; kg++) {
            uint4 N0h, N0l, N1h, N1l;
            if (kg < 7) {
                const uint4* ab =
                    g_hf + (((kggbase + kg + 1) * 4 + mh * 2) * 2) * 32 + lane;
                N0h = __ldcg(ab);
                N0l = __ldcg(ab + 32);
                N1h = __ldcg(ab + 64);
                N1l = __ldcg(ab + 96);
            }
            const int wb = ((kh * 8 + kg) * 16 + nh * 8) * 32 + lane;
#pragma unroll
            for (int nf = 0; nf < 8; nf++) {
                uint4 w = sW[wb + nf * 32];
                mma_bf16(acc[0][nf], A0h, w.x, w.y);   // hi*hi
                mma_bf16(acc[0][nf], A0l, w.x, w.y);   // lo*hi
                mma_bf16(acc[0][nf], A0h, w.z, w.w);   // hi*lo
                mma_bf16(acc[1][nf], A1h, w.x, w.y);
                mma_bf16(acc[1][nf], A1l, w.x, w.y);
                mma_bf16(acc[1][nf], A1h, w.z, w.w);
            }
            if (kg < 7) { A0h = N0h; A0l = N0l; A1h = N1h; A1l = N1l; }
        }

        // write split-K partials (fp32)
        {
            float* pb = &g_part[pk][0][0];
            const int cb = nt * 128 + nh * 64 + (lane & 3) * 2;
#pragma unroll
            for (int mi = 0; mi < 2; mi++) {
                const int r = mh * 32 + mi * 16 + (lane >> 2);
#pragma unroll
                for (int nf = 0; nf < 8; nf++) {
                    const int c = cb + nf * 8;
                    *(float2*)&pb[(size_t)r * DH + c] =
                        make_float2(acc[mi][nf][0], acc[mi][nf][1]);
                    *(float2*)&pb[(size_t)(r + 8) * DH + c] =
                        make_float2(acc[mi][nf][2], acc[mi][nf][3]);
                }
            }
        }
        grid_bar();

        epilogue(s);
        grid_bar();
    }
}

// ---------------------------------------------------------------------------
// Kernel 3: y = g_h @ W_h2y^T + b_h2y (fp32, small) — unchanged
// ---------------------------------------------------------------------------
__global__ __launch_bounds__(128) void k_out(const float* __restrict__ W,
                                             const float* __restrict__ bias,
                                             float* __restrict__ Y) {
    __shared__ float Hs[16][32];
    __shared__ float Ws[16][32];
    const int K  = DH;
    const int n0 = blockIdx.x * 32;
    const int m0 = blockIdx.y * 32;
    const int t  = threadIdx.x;
    const int nx = t & 15, my = t >> 4;
    const float* __restrict__ Hin = g_h;
    const int lrow = t >> 2;
    const int lkq  = t & 3;

    float2 acc[2][2] = { { make_float2(0.f, 0.f), make_float2(0.f, 0.f) },
                         { make_float2(0.f, 0.f), make_float2(0.f, 0.f) } };

    for (int k0 = 0; k0 < K; k0 += 16) {
        float4 va = *(const float4*)(Hin + (size_t)(m0 + lrow) * K + k0 + lkq * 4);
        float4 vb = *(const float4*)(W   + (size_t)(n0 + lrow) * K + k0 + lkq * 4);
        __syncthreads();
        Hs[lkq*4+0][lrow] = va.x; Hs[lkq*4+1][lrow] = va.y;
        Hs[lkq*4+2][lrow] = va.z; Hs[lkq*4+3][lrow] = va.w;
        Ws[lkq*4+0][lrow] = vb.x; Ws[lkq*4+1][lrow] = vb.y;
        Ws[lkq*4+2][lrow] = vb.z; Ws[lkq*4+3][lrow] = vb.w;
        __syncthreads();

#pragma unroll
        for (int kk = 0; kk < 16; kk++) {
            float4 a = *(const float4*)&Hs[kk][my*4];
            float2 bq = *(const float2*)&Ws[kk][nx*2];
            float2 ap0 = make_float2(a.x, a.y), ap1 = make_float2(a.z, a.w);
            float2 b0  = make_float2(bq.x, bq.x), b1  = make_float2(bq.y, bq.y);
            acc[0][0] = ffma2(ap0, b0, acc[0][0]);
            acc[1][0] = ffma2(ap1, b0, acc[1][0]);
            acc[0][1] = ffma2(ap0, b1, acc[0][1]);
            acc[1][1] = ffma2(ap1, b1, acc[1][1]);
        }
    }

    const int c0 = n0 + nx*2;
    float2 bb = *(const float2*)(bias + c0);
#pragma unroll
    for (int i = 0; i < 4; i++) {
        int m = m0 + my*4 + i;
        float v0 = (i & 1) ? acc[i>>1][0].y : acc[i>>1][0].x;
        float v1 = (i & 1) ? acc[i>>1][1].y : acc[i>>1][1].x;
        float2 o = make_float2(v0 + bb.x, v1 + bb.y);
        *(float2*)(Y + (size_t)m * DOUT + c0) = o;
    }
}

// ---------------------------------------------------------------------------
extern "C" void kernel_launch(void* const* d_in, const int* in_sizes, int n_in,
                              void* d_out, int out_size) {
    (void)in_sizes; (void)n_in; (void)out_size;
    const float* x     = (const float*)d_in[0];
    const float* W_x2h = (const float*)d_in[1];
    const float* b_x2h = (const float*)d_in[2];
    const float* W_h2h = (const float*)d_in[3];
    const float* W_h2y = (const float*)d_in[4];
    const float* b_h2y = (const float*)d_in[5];
    float* y = (float*)d_out;

    // allow 128KB dynamic smem for the persistent kernel
    cudaFuncSetAttribute(k_recur, cudaFuncAttributeMaxDynamicSharedMemorySize,
                         WTILE_U4 * sizeof(uint4));

    // 1) input projection (fp32) + W bf16 hi/lo fragment pack
    k_xh<<<dim3(DH / 128, M1 / 128), 256>>>(x, W_x2h, b_x2h);
    k_packw<<<(NBLK * WTILE_U4) / 256, 256>>>(W_h2h);

    // 2) all 512 recurrence steps in ONE persistent kernel (bf16x3 MMA,
    //    W-in-SMEM persistent, L2-direct A fragments, 16-way split-K)
    k_recur<<<NBLK, NTHR, WTILE_U4 * sizeof(uint4)>>>();

    // 3) output projection
    k_out<<<dim3(DOUT / 32, B_ / 32), 128>>>(W_h2y, b_h2y, y);
}

// round 6
// speedup vs baseline: 4.6828x; 1.0023x over previous
#include <cuda_runtime.h>
#include <cuda_bf16.h>
#include <cstdint>
#include <cstddef>

#define B_   64
#define T_   512
#define DIN  1024
#define DH   2048
#define DOUT 1024
#define M1   (B_ * T_)   // 32768

// Recurrence persistent kernel: 128 blocks = 16 ntiles(128 col) x 8 kchunks(256 K)
#define NBLK    128
#define NTHR    256      // 8 warps: (kh, mh, nh)
#define KGG     128      // k16-groups over DH
#define WTILE_U4 8192    // W tile uint4s per block (128KB)

// ---------------------------------------------------------------------------
// Device globals (allocation-free scratch)
// ---------------------------------------------------------------------------
__device__ float    g_xh[(size_t)M1 * DH];        // 256 MB input projection (fp32)
__device__ float    g_h[B_ * DH];                 // final hidden state (fp32)
// W_h2h bf16 hi/lo packed in m16n8k16 B-fragment order, per block tile:
// uint4 {b0_hi, b1_hi, b0_lo, b1_lo} per (block, kg, nfl, lane)
__device__ uint4    g_Wf[(size_t)NBLK * WTILE_U4];   // 16 MB
// h bf16 hi/lo packed in A-fragment order:
// uint4 {a0,a1,a2,a3} per (kgg, mf, plane, lane)
__device__ uint4    g_hf[KGG * 4 * 2 * 32];          // 512 KB
__device__ float    g_part[16][B_][DH];              // split-K partials, 8 MB
__device__ unsigned g_bar_count;
__device__ unsigned g_bar_phase;

__device__ __forceinline__ float2 ffma2(float2 a, float2 b, float2 c) {
    float2 d;
    asm("fma.rn.f32x2 %0, %1, %2, %3;"
        : "=l"(reinterpret_cast<unsigned long long&>(d))
        : "l"(reinterpret_cast<unsigned long long&>(a)),
          "l"(reinterpret_cast<unsigned long long&>(b)),
          "l"(reinterpret_cast<unsigned long long&>(c)));
    return d;
}

// split (v0, v1) into bf16 hi plane + bf16 lo (residual) plane, packed bf16x2
__device__ __forceinline__ void split2(float v0, float v1,
                                       unsigned& hi, unsigned& lo) {
    __nv_bfloat162 h2 = __floats2bfloat162_rn(v0, v1);
    float2 hf = __bfloat1622float2(h2);
    __nv_bfloat162 l2 = __floats2bfloat162_rn(v0 - hf.x, v1 - hf.y);
    hi = *reinterpret_cast<unsigned*>(&h2);
    lo = *reinterpret_cast<unsigned*>(&l2);
}

__device__ __forceinline__ void mma_bf16(float* c, const uint4& a,
                                         unsigned b0, unsigned b1) {
    asm volatile(
        "mma.sync.aligned.m16n8k16.row.col.f32.bf16.bf16.f32 "
        "{%0,%1,%2,%3}, {%4,%5,%6,%7}, {%8,%9}, {%0,%1,%2,%3};"
        : "+f"(c[0]), "+f"(c[1]), "+f"(c[2]), "+f"(c[3])
        : "r"(a.x), "r"(a.y), "r"(a.z), "r"(a.w), "r"(b0), "r"(b1));
}

// ---------------------------------------------------------------------------
// Kernel 1: g_xh = x @ W_x2h^T + b_x2h  (fp32, 128x128 tile, FFMA2) — unchanged
// ---------------------------------------------------------------------------
__global__ __launch_bounds__(256) void k_xh(const float* __restrict__ A,
                                            const float* __restrict__ W,
                                            const float* __restrict__ bias) {
    __shared__ float As[16][128];
    __shared__ float Bs[16][128];
    const int K  = DIN;
    const int N  = DH;
    const int m0 = blockIdx.y * 128;
    const int n0 = blockIdx.x * 128;
    const int t  = threadIdx.x;
    const int tx = t & 15, ty = t >> 4;

    float2 acc[4][8];
#pragma unroll
    for (int p = 0; p < 4; p++)
#pragma unroll
        for (int j = 0; j < 8; j++) acc[p][j] = make_float2(0.f, 0.f);

    const int lrow = t >> 2;
    const int lkq  = t & 3;

    for (int k0 = 0; k0 < K; k0 += 16) {
        float4 a0 = *(const float4*)(A + (size_t)(m0 + lrow)      * K + k0 + lkq * 4);
        float4 a1 = *(const float4*)(A + (size_t)(m0 + 64 + lrow) * K + k0 + lkq * 4);
        float4 b0 = *(const float4*)(W + (size_t)(n0 + lrow)      * K + k0 + lkq * 4);
        float4 b1 = *(const float4*)(W + (size_t)(n0 + 64 + lrow) * K + k0 + lkq * 4);
        __syncthreads();
        As[lkq*4+0][lrow] = a0.x; As[lkq*4+1][lrow] = a0.y;
        As[lkq*4+2][lrow] = a0.z; As[lkq*4+3][lrow] = a0.w;
        As[lkq*4+0][64+lrow] = a1.x; As[lkq*4+1][64+lrow] = a1.y;
        As[lkq*4+2][64+lrow] = a1.z; As[lkq*4+3][64+lrow] = a1.w;
        Bs[lkq*4+0][lrow] = b0.x; Bs[lkq*4+1][lrow] = b0.y;
        Bs[lkq*4+2][lrow] = b0.z; Bs[lkq*4+3][lrow] = b0.w;
        Bs[lkq*4+0][64+lrow] = b1.x; Bs[lkq*4+1][64+lrow] = b1.y;
        Bs[lkq*4+2][64+lrow] = b1.z; Bs[lkq*4+3][64+lrow] = b1.w;
        __syncthreads();

#pragma unroll
        for (int kk = 0; kk < 16; kk++) {
            float4 av0 = *(const float4*)&As[kk][ty*4];
            float4 av1 = *(const float4*)&As[kk][64 + ty*4];
            float4 bv0 = *(const float4*)&Bs[kk][tx*4];
            float4 bv1 = *(const float4*)&Bs[kk][64 + tx*4];
            float2 ap[4] = { make_float2(av0.x, av0.y), make_float2(av0.z, av0.w),
                             make_float2(av1.x, av1.y), make_float2(av1.z, av1.w) };
            float  bb[8] = { bv0.x, bv0.y, bv0.z, bv0.w, bv1.x, bv1.y, bv1.z, bv1.w };
#pragma unroll
            for (int j = 0; j < 8; j++) {
                float2 b2 = make_float2(bb[j], bb[j]);
#pragma unroll
                for (int p = 0; p < 4; p++)
                    acc[p][j] = ffma2(ap[p], b2, acc[p][j]);
            }
        }
    }

    float4 bias0 = *(const float4*)(bias + n0 + tx*4);
    float4 bias1 = *(const float4*)(bias + n0 + 64 + tx*4);
    float bv[8] = { bias0.x, bias0.y, bias0.z, bias0.w,
                    bias1.x, bias1.y, bias1.z, bias1.w };
#pragma unroll
    for (int i = 0; i < 8; i++) {
        int lr = (i < 4) ? (ty*4 + i) : (64 + ty*4 + (i - 4));
        int p  = i >> 1;
        float* Cp = g_xh + (size_t)(m0 + lr) * N + n0 + tx*4;
        float4 s0, s1;
        if (i & 1) {
            s0 = make_float4(acc[p][0].y + bv[0], acc[p][1].y + bv[1],
                             acc[p][2].y + bv[2], acc[p][3].y + bv[3]);
            s1 = make_float4(acc[p][4].y + bv[4], acc[p][5].y + bv[5],
                             acc[p][6].y + bv[6], acc[p][7].y + bv[7]);
        } else {
            s0 = make_float4(acc[p][0].x + bv[0], acc[p][1].x + bv[1],
                             acc[p][2].x + bv[2], acc[p][3].x + bv[3]);
            s1 = make_float4(acc[p][4].x + bv[4], acc[p][5].x + bv[5],
                             acc[p][6].x + bv[6], acc[p][7].x + bv[7]);
        }
        *(float4*)Cp        = s0;
        *(float4*)(Cp + 64) = s1;
    }
}

// ---------------------------------------------------------------------------
// Pack W_h2h into bf16 hi/lo B-fragment order (per-block 128KB tiles).
// ---------------------------------------------------------------------------
__global__ void k_packw(const float* __restrict__ W) {
    size_t u = (size_t)blockIdx.x * 256 + threadIdx.x;   // 0 .. 1M-1
    int b    = (int)(u >> 13);
    int r    = (int)(u & 8191);
    int kg   = r >> 9;          // 0..15
    int nfl  = (r >> 5) & 15;   // 0..15
    int lane = r & 31;
    int nt = b >> 3, kch = b & 7;
    int n = nt * 128 + nfl * 8 + (lane >> 2);
    int k = kch * 256 + kg * 16 + (lane & 3) * 2;
    const float* row = W + (size_t)n * DH;
    float w0 = row[k],     w1 = row[k + 1];
    float w2 = row[k + 8], w3 = row[k + 9];
    uint4 v;
    unsigned lo01, lo89;
    split2(w0, w1, v.x, lo01);
    split2(w2, w3, v.y, lo89);
    v.z = lo01;
    v.w = lo89;
    g_Wf[u] = v;
}

// ---------------------------------------------------------------------------
// Persistent recurrence kernel: bf16x3 mma.m16n8k16, W tile persistent in SMEM,
// 8 warps (2/SMSP), A fragments L2-direct, 16-way split-K partials.
// ---------------------------------------------------------------------------
__global__ __launch_bounds__(NTHR, 1) void k_recur() {
    extern __shared__ uint4 sW[];   // 8192 uint4 = 128 KB

    const int tid  = threadIdx.x;
    const int b    = blockIdx.x;
    const int warp = tid >> 5;
    const int lane = tid & 31;
    const int kh = warp >> 2;          // k-half (0/1): 128 K each
    const int mh = (warp >> 1) & 1;    // m-half: rows mh*32..+31
    const int nh = warp & 1;           // n-half: cols nh*64..+63
    const int nt  = b >> 3;            // ntile 0..15
    const int kch = b & 7;             // kchunk 0..7
    const int pk  = kch * 2 + kh;      // partial buffer index

    // Load persistent W tile into SMEM (once)
    {
        const uint4* wsrc = g_Wf + (size_t)b * WTILE_U4;
        for (int i = tid; i < WTILE_U4; i += NTHR) sW[i] = __ldg(wsrc + i);
    }

    // replay-safe grid barrier
    unsigned bar_base;
    asm volatile("ld.acquire.gpu.global.u32 %0, [%1];"
                 : "=r"(bar_base) : "l"(&g_bar_phase));
    unsigned bar_t = 0;

    auto grid_bar = [&]() {
        bar_t++;
        __syncthreads();
        __threadfence();
        if (tid == 0) {
            unsigned arr = atomicAdd(&g_bar_count, 1);
            if (arr == NBLK - 1) {
                atomicExch(&g_bar_count, 0);
                __threadfence();
                atomicAdd(&g_bar_phase, 1);
            } else {
                unsigned p;
                do {
                    __nanosleep(32);
                    asm volatile("ld.acquire.gpu.global.u32 %0, [%1];"
                                 : "=r"(p) : "l"(&g_bar_phase));
                } while (p - bar_base < bar_t);
            }
        }
        __syncthreads();
    };

    // Epilogue mapping: block b owns kgg = b (16 h-columns), threads 0..127
    const int elane = tid & 31;
    const int emf   = (tid >> 5) & 3;
    const int er    = emf * 16 + (elane >> 2);       // row (and +8)
    const int ek0   = b * 16 + (elane & 3) * 2;      // col (and +1, +8, +9)
    uint4* hf_hi = g_hf + ((b * 4 + emf) * 2 + 0) * 32 + elane;
    uint4* hf_lo = g_hf + ((b * 4 + emf) * 2 + 1) * 32 + elane;

    auto epilogue = [&](int s) {   // computes h_s from xh_{s-1} (+ partials if s>1)
        if (tid < 128) {
            const float* x0 = &g_xh[((size_t)er * T_ + (s - 1)) * DH + ek0];
            const float* x1 = &g_xh[((size_t)(er + 8) * T_ + (s - 1)) * DH + ek0];
            float2 v00 = __ldg((const float2*)x0);        // (er,   k0..k0+1)
            float2 v01 = __ldg((const float2*)(x0 + 8));  // (er,   k0+8..+9)
            float2 v10 = __ldg((const float2*)x1);        // (er+8, k0..k0+1)
            float2 v11 = __ldg((const float2*)(x1 + 8));  // (er+8, k0+8..+9)
            if (s > 1) {
#pragma unroll
                for (int p = 0; p < 16; p++) {
                    const float* pb = &g_part[p][0][0];
                    const float* p0 = pb + (size_t)er * DH + ek0;
                    const float* p1 = pb + (size_t)(er + 8) * DH + ek0;
                    float2 q;
                    q = __ldcg((const float2*)p0);       v00.x += q.x; v00.y += q.y;
                    q = __ldcg((const float2*)(p0 + 8)); v01.x += q.x; v01.y += q.y;
                    q = __ldcg((const float2*)p1);       v10.x += q.x; v10.y += q.y;
                    q = __ldcg((const float2*)(p1 + 8)); v11.x += q.x; v11.y += q.y;
                }
            }
            v00.x = fmaxf(v00.x, 0.f); v00.y = fmaxf(v00.y, 0.f);
            v01.x = fmaxf(v01.x, 0.f); v01.y = fmaxf(v01.y, 0.f);
            v10.x = fmaxf(v10.x, 0.f); v10.y = fmaxf(v10.y, 0.f);
            v11.x = fmaxf(v11.x, 0.f); v11.y = fmaxf(v11.y, 0.f);
            uint4 hi, lo;
            split2(v00.x, v00.y, hi.x, lo.x);   // a0: (r,   k0,k0+1)
            split2(v10.x, v10.y, hi.y, lo.y);   // a1: (r+8, k0,k0+1)
            split2(v01.x, v01.y, hi.z, lo.z);   // a2: (r,   k0+8,k0+9)
            split2(v11.x, v11.y, hi.w, lo.w);   // a3: (r+8, k0+8,k0+9)
            *hf_hi = hi;
            *hf_lo = lo;
            if (s == T_) {
                *(float2*)&g_h[(size_t)er * DH + ek0]           = v00;
                *(float2*)&g_h[(size_t)er * DH + ek0 + 8]       = v01;
                *(float2*)&g_h[(size_t)(er + 8) * DH + ek0]     = v10;
                *(float2*)&g_h[(size_t)(er + 8) * DH + ek0 + 8] = v11;
            }
        }
    };

    epilogue(1);          // h_1 = relu(xh_0)
    grid_bar();

    const int kggbase = kch * 16 + kh * 8;

    for (int s = 2; s <= T_; s++) {
        // ---- MMA phase: partial[pk] = h_{s-1}[:, kslice] @ W[ntile, kslice]^T
        float acc[2][8][4];
#pragma unroll
        for (int mi = 0; mi < 2; mi++)
#pragma unroll
            for (int nf = 0; nf < 8; nf++)
#pragma unroll
                for (int i = 0; i < 4; i++) acc[mi][nf][i] = 0.f;

        // prefetch kg=0 A fragments
        const uint4* ab0 = g_hf + ((kggbase * 4 + mh * 2) * 2) * 32 + lane;
        uint4 A0h = __ldcg(ab0);
        uint4 A0l = __ldcg(ab0 + 32);
        uint4 A1h = __ldcg(ab0 + 64);
        uint4 A1l = __ldcg(ab0 + 96);

#pragma unroll
        for (int kg = 0; kg < 8; kg++) {
            uint4 N0h, N0l, N1h, N1l;
            if (kg < 7) {
                const uint4* ab =
                    g_hf + (((kggbase + kg + 1) * 4 + mh * 2) * 2) * 32 + lane;
                N0h = __ldcg(ab);
                N0l = __ldcg(ab + 32);
                N1h = __ldcg(ab + 64);
                N1l = __ldcg(ab + 96);
            }
            const int wb = ((kh * 8 + kg) * 16 + nh * 8) * 32 + lane;
#pragma unroll
            for (int nf = 0; nf < 8; nf++) {
                uint4 w = sW[wb + nf * 32];
                mma_bf16(acc[0][nf], A0h, w.x, w.y);   // hi*hi
                mma_bf16(acc[0][nf], A0l, w.x, w.y);   // lo*hi
                mma_bf16(acc[0][nf], A0h, w.z, w.w);   // hi*lo
                mma_bf16(acc[1][nf], A1h, w.x, w.y);
                mma_bf16(acc[1][nf], A1l, w.x, w.y);
                mma_bf16(acc[1][nf], A1h, w.z, w.w);
            }
            if (kg < 7) { A0h = N0h; A0l = N0l; A1h = N1h; A1l = N1l; }
        }

        // write split-K partials (fp32)
        {
            float* pb = &g_part[pk][0][0];
            const int cb = nt * 128 + nh * 64 + (lane & 3) * 2;
#pragma unroll
            for (int mi = 0; mi < 2; mi++) {
                const int r = mh * 32 + mi * 16 + (lane >> 2);
#pragma unroll
                for (int nf = 0; nf < 8; nf++) {
                    const int c = cb + nf * 8;
                    *(float2*)&pb[(size_t)r * DH + c] =
                        make_float2(acc[mi][nf][0], acc[mi][nf][1]);
                    *(float2*)&pb[(size_t)(r + 8) * DH + c] =
                        make_float2(acc[mi][nf][2], acc[mi][nf][3]);
                }
            }
        }
        grid_bar();

        epilogue(s);
        grid_bar();
    }
}

// ---------------------------------------------------------------------------
// Kernel 3: y = g_h @ W_h2y^T + b_h2y (fp32, small) — unchanged
// ---------------------------------------------------------------------------
__global__ __launch_bounds__(128) void k_out(const float* __restrict__ W,
                                             const float* __restrict__ bias,
                                             float* __restrict__ Y) {
    __shared__ float Hs[16][32];
    __shared__ float Ws[16][32];
    const int K  = DH;
    const int n0 = blockIdx.x * 32;
    const int m0 = blockIdx.y * 32;
    const int t  = threadIdx.x;
    const int nx = t & 15, my = t >> 4;
    const float* __restrict__ Hin = g_h;
    const int lrow = t >> 2;
    const int lkq  = t & 3;

    float2 acc[2][2] = { { make_float2(0.f, 0.f), make_float2(0.f, 0.f) },
                         { make_float2(0.f, 0.f), make_float2(0.f, 0.f) } };

    for (int k0 = 0; k0 < K; k0 += 16) {
        float4 va = *(const float4*)(Hin + (size_t)(m0 + lrow) * K + k0 + lkq * 4);
        float4 vb = *(const float4*)(W   + (size_t)(n0 + lrow) * K + k0 + lkq * 4);
        __syncthreads();
        Hs[lkq*4+0][lrow] = va.x; Hs[lkq*4+1][lrow] = va.y;
        Hs[lkq*4+2][lrow] = va.z; Hs[lkq*4+3][lrow] = va.w;
        Ws[lkq*4+0][lrow] = vb.x; Ws[lkq*4+1][lrow] = vb.y;
        Ws[lkq*4+2][lrow] = vb.z; Ws[lkq*4+3][lrow] = vb.w;
        __syncthreads();

#pragma unroll
        for (int kk = 0; kk < 16; kk++) {
            float4 a = *(const float4*)&Hs[kk][my*4];
            float2 bq = *(const float2*)&Ws[kk][nx*2];
            float2 ap0 = make_float2(a.x, a.y), ap1 = make_float2(a.z, a.w);
            float2 b0  = make_float2(bq.x, bq.x), b1  = make_float2(bq.y, bq.y);
            acc[0][0] = ffma2(ap0, b0, acc[0][0]);
            acc[1][0] = ffma2(ap1, b0, acc[1][0]);
            acc[0][1] = ffma2(ap0, b1, acc[0][1]);
            acc[1][1] = ffma2(ap1, b1, acc[1][1]);
        }
    }

    const int c0 = n0 + nx*2;
    float2 bb = *(const float2*)(bias + c0);
#pragma unroll
    for (int i = 0; i < 4; i++) {
        int m = m0 + my*4 + i;
        float v0 = (i & 1) ? acc[i>>1][0].y : acc[i>>1][0].x;
        float v1 = (i & 1) ? acc[i>>1][1].y : acc[i>>1][1].x;
        float2 o = make_float2(v0 + bb.x, v1 + bb.y);
        *(float2*)(Y + (size_t)m * DOUT + c0) = o;
    }
}

// ---------------------------------------------------------------------------
extern "C" void kernel_launch(void* const* d_in, const int* in_sizes, int n_in,
                              void* d_out, int out_size) {
    (void)in_sizes; (void)n_in; (void)out_size;
    const float* x     = (const float*)d_in[0];
    const float* W_x2h = (const float*)d_in[1];
    const float* b_x2h = (const float*)d_in[2];
    const float* W_h2h = (const float*)d_in[3];
    const float* W_h2y = (const float*)d_in[4];
    const float* b_h2y = (const float*)d_in[5];
    float* y = (float*)d_out;

    // allow 128KB dynamic smem for the persistent kernel
    cudaFuncSetAttribute(k_recur, cudaFuncAttributeMaxDynamicSharedMemorySize,
                         WTILE_U4 * sizeof(uint4));

    // 1) input projection (fp32) + W bf16 hi/lo fragment pack
    k_xh<<<dim3(DH / 128, M1 / 128), 256>>>(x, W_x2h, b_x2h);
    k_packw<<<(NBLK * WTILE_U4) / 256, 256>>>(W_h2h);

    // 2) all 512 recurrence steps in ONE persistent kernel (bf16x3 MMA,
    //    W-in-SMEM persistent, L2-direct A fragments, 16-way split-K)
    k_recur<<<NBLK, NTHR, WTILE_U4 * sizeof(uint4)>>>();

    // 3) output projection
    k_out<<<dim3(DOUT / 32, B_ / 32), 128>>>(W_h2y, b_h2y, y);
}

// round 7
// speedup vs baseline: 4.6891x; 1.0014x over previous
#include <cuda_runtime.h>
#include <cuda_bf16.h>
#include <cstdint>
#include <cstddef>

#define B_   64
#define T_   512
#define DIN  1024
#define DH   2048
#define DOUT 1024
#define M1   (B_ * T_)   // 32768

// Recurrence persistent kernel: 128 blocks = 16 ntiles(128 col) x 8 kchunks(256 K)
#define NBLK    128
#define NTHR    256      // 8 warps: (kh, mh, nh)
#define KGG     128      // k16-groups over DH
#define WTILE_U4 8192    // W tile uint4s per block (128KB)

// ---------------------------------------------------------------------------
// Device globals (allocation-free scratch)
// ---------------------------------------------------------------------------
__device__ float    g_xh[(size_t)M1 * DH];        // 256 MB input projection (fp32)
__device__ float    g_h[B_ * DH];                 // final hidden state (fp32)
// W_h2h bf16 hi/lo packed in m16n8k16 B-fragment order, per block tile:
// uint4 {b0_hi, b1_hi, b0_lo, b1_lo} per (block, kg, nfl, lane)
__device__ uint4    g_Wf[(size_t)NBLK * WTILE_U4];   // 16 MB
// h bf16 hi/lo packed in A-fragment order:
// uint4 {a0,a1,a2,a3} per (kgg, mf, plane, lane)
__device__ uint4    g_hf[KGG * 4 * 2 * 32];          // 512 KB
__device__ float    g_part[16][B_][DH];              // split-K partials, 8 MB
__device__ unsigned g_bar_count;
__device__ unsigned g_bar_phase;

__device__ __forceinline__ float2 ffma2(float2 a, float2 b, float2 c) {
    float2 d;
    asm("fma.rn.f32x2 %0, %1, %2, %3;"
        : "=l"(reinterpret_cast<unsigned long long&>(d))
        : "l"(reinterpret_cast<unsigned long long&>(a)),
          "l"(reinterpret_cast<unsigned long long&>(b)),
          "l"(reinterpret_cast<unsigned long long&>(c)));
    return d;
}

// split (v0, v1) into bf16 hi plane + bf16 lo (residual) plane, packed bf16x2
__device__ __forceinline__ void split2(float v0, float v1,
                                       unsigned& hi, unsigned& lo) {
    __nv_bfloat162 h2 = __floats2bfloat162_rn(v0, v1);
    float2 hf = __bfloat1622float2(h2);
    __nv_bfloat162 l2 = __floats2bfloat162_rn(v0 - hf.x, v1 - hf.y);
    hi = *reinterpret_cast<unsigned*>(&h2);
    lo = *reinterpret_cast<unsigned*>(&l2);
}

__device__ __forceinline__ void mma_bf16(float* c, const uint4& a,
                                         unsigned b0, unsigned b1) {
    asm volatile(
        "mma.sync.aligned.m16n8k16.row.col.f32.bf16.bf16.f32 "
        "{%0,%1,%2,%3}, {%4,%5,%6,%7}, {%8,%9}, {%0,%1,%2,%3};"
        : "+f"(c[0]), "+f"(c[1]), "+f"(c[2]), "+f"(c[3])
        : "r"(a.x), "r"(a.y), "r"(a.z), "r"(a.w), "r"(b0), "r"(b1));
}

// ---------------------------------------------------------------------------
// Kernel 1: g_xh = x @ W_x2h^T + b_x2h  (fp32, 128x128 tile, FFMA2) — unchanged
// ---------------------------------------------------------------------------
__global__ __launch_bounds__(256) void k_xh(const float* __restrict__ A,
                                            const float* __restrict__ W,
                                            const float* __restrict__ bias) {
    __shared__ float As[16][128];
    __shared__ float Bs[16][128];
    const int K  = DIN;
    const int N  = DH;
    const int m0 = blockIdx.y * 128;
    const int n0 = blockIdx.x * 128;
    const int t  = threadIdx.x;
    const int tx = t & 15, ty = t >> 4;

    float2 acc[4][8];
#pragma unroll
    for (int p = 0; p < 4; p++)
#pragma unroll
        for (int j = 0; j < 8; j++) acc[p][j] = make_float2(0.f, 0.f);

    const int lrow = t >> 2;
    const int lkq  = t & 3;

    for (int k0 = 0; k0 < K; k0 += 16) {
        float4 a0 = *(const float4*)(A + (size_t)(m0 + lrow)      * K + k0 + lkq * 4);
        float4 a1 = *(const float4*)(A + (size_t)(m0 + 64 + lrow) * K + k0 + lkq * 4);
        float4 b0 = *(const float4*)(W + (size_t)(n0 + lrow)      * K + k0 + lkq * 4);
        float4 b1 = *(const float4*)(W + (size_t)(n0 + 64 + lrow) * K + k0 + lkq * 4);
        __syncthreads();
        As[lkq*4+0][lrow] = a0.x; As[lkq*4+1][lrow] = a0.y;
        As[lkq*4+2][lrow] = a0.z; As[lkq*4+3][lrow] = a0.w;
        As[lkq*4+0][64+lrow] = a1.x; As[lkq*4+1][64+lrow] = a1.y;
        As[lkq*4+2][64+lrow] = a1.z; As[lkq*4+3][64+lrow] = a1.w;
        Bs[lkq*4+0][lrow] = b0.x; Bs[lkq*4+1][lrow] = b0.y;
        Bs[lkq*4+2][lrow] = b0.z; Bs[lkq*4+3][lrow] = b0.w;
        Bs[lkq*4+0][64+lrow] = b1.x; Bs[lkq*4+1][64+lrow] = b1.y;
        Bs[lkq*4+2][64+lrow] = b1.z; Bs[lkq*4+3][64+lrow] = b1.w;
        __syncthreads();

#pragma unroll
        for (int kk = 0; kk < 16; kk++) {
            float4 av0 = *(const float4*)&As[kk][ty*4];
            float4 av1 = *(const float4*)&As[kk][64 + ty*4];
            float4 bv0 = *(const float4*)&Bs[kk][tx*4];
            float4 bv1 = *(const float4*)&Bs[kk][64 + tx*4];
            float2 ap[4] = { make_float2(av0.x, av0.y), make_float2(av0.z, av0.w),
                             make_float2(av1.x, av1.y), make_float2(av1.z, av1.w) };
            float  bb[8] = { bv0.x, bv0.y, bv0.z, bv0.w, bv1.x, bv1.y, bv1.z, bv1.w };
#pragma unroll
            for (int j = 0; j < 8; j++) {
                float2 b2 = make_float2(bb[j], bb[j]);
#pragma unroll
                for (int p = 0; p < 4; p++)
                    acc[p][j] = ffma2(ap[p], b2, acc[p][j]);
            }
        }
    }

    float4 bias0 = *(const float4*)(bias + n0 + tx*4);
    float4 bias1 = *(const float4*)(bias + n0 + 64 + tx*4);
    float bv[8] = { bias0.x, bias0.y, bias0.z, bias0.w,
                    bias1.x, bias1.y, bias1.z, bias1.w };
#pragma unroll
    for (int i = 0; i < 8; i++) {
        int lr = (i < 4) ? (ty*4 + i) : (64 + ty*4 + (i - 4));
        int p  = i >> 1;
        float* Cp = g_xh + (size_t)(m0 + lr) * N + n0 + tx*4;
        float4 s0, s1;
        if (i & 1) {
            s0 = make_float4(acc[p][0].y + bv[0], acc[p][1].y + bv[1],
                             acc[p][2].y + bv[2], acc[p][3].y + bv[3]);
            s1 = make_float4(acc[p][4].y + bv[4], acc[p][5].y + bv[5],
                             acc[p][6].y + bv[6], acc[p][7].y + bv[7]);
        } else {
            s0 = make_float4(acc[p][0].x + bv[0], acc[p][1].x + bv[1],
                             acc[p][2].x + bv[2], acc[p][3].x + bv[3]);
            s1 = make_float4(acc[p][4].x + bv[4], acc[p][5].x + bv[5],
                             acc[p][6].x + bv[6], acc[p][7].x + bv[7]);
        }
        *(float4*)Cp        = s0;
        *(float4*)(Cp + 64) = s1;
    }
}

// ---------------------------------------------------------------------------
// Pack W_h2h into bf16 hi/lo B-fragment order (per-block 128KB tiles).
// ---------------------------------------------------------------------------
__global__ void k_packw(const float* __restrict__ W) {
    size_t u = (size_t)blockIdx.x * 256 + threadIdx.x;   // 0 .. 1M-1
    int b    = (int)(u >> 13);
    int r    = (int)(u & 8191);
    int kg   = r >> 9;          // 0..15
    int nfl  = (r >> 5) & 15;   // 0..15
    int lane = r & 31;
    int nt = b >> 3, kch = b & 7;
    int n = nt * 128 + nfl * 8 + (lane >> 2);
    int k = kch * 256 + kg * 16 + (lane & 3) * 2;
    const float* row = W + (size_t)n * DH;
    float w0 = row[k],     w1 = row[k + 1];
    float w2 = row[k + 8], w3 = row[k + 9];
    uint4 v;
    unsigned lo01, lo89;
    split2(w0, w1, v.x, lo01);
    split2(w2, w3, v.y, lo89);
    v.z = lo01;
    v.w = lo89;
    g_Wf[u] = v;
}

// ---------------------------------------------------------------------------
// Persistent recurrence kernel: bf16x3 mma.m16n8k16, W tile persistent in SMEM,
// 8 warps (2/SMSP), A fragments L2-direct, 16-way split-K partials.
// ---------------------------------------------------------------------------
__global__ __launch_bounds__(NTHR, 1) void k_recur() {
    extern __shared__ uint4 sW[];   // 8192 uint4 = 128 KB

    const int tid  = threadIdx.x;
    const int b    = blockIdx.x;
    const int warp = tid >> 5;
    const int lane = tid & 31;
    const int kh = warp >> 2;          // k-half (0/1): 128 K each
    const int mh = (warp >> 1) & 1;    // m-half: rows mh*32..+31
    const int nh = warp & 1;           // n-half: cols nh*64..+63
    const int nt  = b >> 3;            // ntile 0..15
    const int kch = b & 7;             // kchunk 0..7
    const int pk  = kch * 2 + kh;      // partial buffer index

    // Load persistent W tile into SMEM (once)
    {
        const uint4* wsrc = g_Wf + (size_t)b * WTILE_U4;
        for (int i = tid; i < WTILE_U4; i += NTHR) sW[i] = __ldg(wsrc + i);
    }

    // replay-safe grid barrier
    unsigned bar_base;
    asm volatile("ld.acquire.gpu.global.u32 %0, [%1];"
                 : "=r"(bar_base) : "l"(&g_bar_phase));
    unsigned bar_t = 0;

    auto grid_bar = [&]() {
        bar_t++;
        __syncthreads();
        __threadfence();
        if (tid == 0) {
            unsigned arr = atomicAdd(&g_bar_count, 1);
            if (arr == NBLK - 1) {
                atomicExch(&g_bar_count, 0);
                __threadfence();
                atomicAdd(&g_bar_phase, 1);
            } else {
                unsigned p;
                do {
                    __nanosleep(32);
                    asm volatile("ld.acquire.gpu.global.u32 %0, [%1];"
                                 : "=r"(p) : "l"(&g_bar_phase));
                } while (p - bar_base < bar_t);
            }
        }
        __syncthreads();
    };

    // Epilogue mapping: block b owns kgg = b (16 h-columns), threads 0..127
    const int elane = tid & 31;
    const int emf   = (tid >> 5) & 3;
    const int er    = emf * 16 + (elane >> 2);       // row (and +8)
    const int ek0   = b * 16 + (elane & 3) * 2;      // col (and +1, +8, +9)
    uint4* hf_hi = g_hf + ((b * 4 + emf) * 2 + 0) * 32 + elane;
    uint4* hf_lo = g_hf + ((b * 4 + emf) * 2 + 1) * 32 + elane;

    auto epilogue = [&](int s) {   // computes h_s from xh_{s-1} (+ partials if s>1)
        if (tid < 128) {
            const float* x0 = &g_xh[((size_t)er * T_ + (s - 1)) * DH + ek0];
            const float* x1 = &g_xh[((size_t)(er + 8) * T_ + (s - 1)) * DH + ek0];
            float2 v00 = __ldg((const float2*)x0);        // (er,   k0..k0+1)
            float2 v01 = __ldg((const float2*)(x0 + 8));  // (er,   k0+8..+9)
            float2 v10 = __ldg((const float2*)x1);        // (er+8, k0..k0+1)
            float2 v11 = __ldg((const float2*)(x1 + 8));  // (er+8, k0+8..+9)
            if (s > 1) {
#pragma unroll
                for (int p = 0; p < 16; p++) {
                    const float* pb = &g_part[p][0][0];
                    const float* p0 = pb + (size_t)er * DH + ek0;
                    const float* p1 = pb + (size_t)(er + 8) * DH + ek0;
                    float2 q;
                    q = __ldcg((const float2*)p0);       v00.x += q.x; v00.y += q.y;
                    q = __ldcg((const float2*)(p0 + 8)); v01.x += q.x; v01.y += q.y;
                    q = __ldcg((const float2*)p1);       v10.x += q.x; v10.y += q.y;
                    q = __ldcg((const float2*)(p1 + 8)); v11.x += q.x; v11.y += q.y;
                }
            }
            v00.x = fmaxf(v00.x, 0.f); v00.y = fmaxf(v00.y, 0.f);
            v01.x = fmaxf(v01.x, 0.f); v01.y = fmaxf(v01.y, 0.f);
            v10.x = fmaxf(v10.x, 0.f); v10.y = fmaxf(v10.y, 0.f);
            v11.x = fmaxf(v11.x, 0.f); v11.y = fmaxf(v11.y, 0.f);
            uint4 hi, lo;
            split2(v00.x, v00.y, hi.x, lo.x);   // a0: (r,   k0,k0+1)
            split2(v10.x, v10.y, hi.y, lo.y);   // a1: (r+8, k0,k0+1)
            split2(v01.x, v01.y, hi.z, lo.z);   // a2: (r,   k0+8,k0+9)
            split2(v11.x, v11.y, hi.w, lo.w);   // a3: (r+8, k0+8,k0+9)
            *hf_hi = hi;
            *hf_lo = lo;
            if (s == T_) {
                *(float2*)&g_h[(size_t)er * DH + ek0]           = v00;
                *(float2*)&g_h[(size_t)er * DH + ek0 + 8]       = v01;
                *(float2*)&g_h[(size_t)(er + 8) * DH + ek0]     = v10;
                *(float2*)&g_h[(size_t)(er + 8) * DH + ek0 + 8] = v11;
            }
        }
    };

    epilogue(1);          // h_1 = relu(xh_0)
    grid_bar();

    const int kggbase = kch * 16 + kh * 8;

    for (int s = 2; s <= T_; s++) {
        // ---- MMA phase: partial[pk] = h_{s-1}[:, kslice] @ W[ntile, kslice]^T
        float acc[2][8][4];
#pragma unroll
        for (int mi = 0; mi < 2; mi++)
#pragma unroll
            for (int nf = 0; nf < 8; nf++)
#pragma unroll
                for (int i = 0; i < 4; i++) acc[mi][nf][i] = 0.f;

        // prefetch kg=0 A fragments
        const uint4* ab0 = g_hf + ((kggbase * 4 + mh * 2) * 2) * 32 + lane;
        uint4 A0h = __ldcg(ab0);
        uint4 A0l = __ldcg(ab0 + 32);
        uint4 A1h = __ldcg(ab0 + 64);
        uint4 A1l = __ldcg(ab0 + 96);

#pragma unroll
        for (int kg = 0; kg < 8; kg++) {
            uint4 N0h, N0l, N1h, N1l;
            if (kg < 7) {
                const uint4* ab =
                    g_hf + (((kggbase + kg + 1) * 4 + mh * 2) * 2) * 32 + lane;
                N0h = __ldcg(ab);
                N0l = __ldcg(ab + 32);
                N1h = __ldcg(ab + 64);
                N1l = __ldcg(ab + 96);
            }
            const int wb = ((kh * 8 + kg) * 16 + nh * 8) * 32 + lane;
#pragma unroll
            for (int nf = 0; nf < 8; nf++) {
                uint4 w = sW[wb + nf * 32];
                mma_bf16(acc[0][nf], A0h, w.x, w.y);   // hi*hi
                mma_bf16(acc[0][nf], A0l, w.x, w.y);   // lo*hi
                mma_bf16(acc[0][nf], A0h, w.z, w.w);   // hi*lo
                mma_bf16(acc[1][nf], A1h, w.x, w.y);
                mma_bf16(acc[1][nf], A1l, w.x, w.y);
                mma_bf16(acc[1][nf], A1h, w.z, w.w);
            }
            if (kg < 7) { A0h = N0h; A0l = N0l; A1h = N1h; A1l = N1l; }
        }

        // write split-K partials (fp32)
        {
            float* pb = &g_part[pk][0][0];
            const int cb = nt * 128 + nh * 64 + (lane & 3) * 2;
#pragma unroll
            for (int mi = 0; mi < 2; mi++) {
                const int r = mh * 32 + mi * 16 + (lane >> 2);
#pragma unroll
                for (int nf = 0; nf < 8; nf++) {
                    const int c = cb + nf * 8;
                    *(float2*)&pb[(size_t)r * DH + c] =
                        make_float2(acc[mi][nf][0], acc[mi][nf][1]);
                    *(float2*)&pb[(size_t)(r + 8) * DH + c] =
                        make_float2(acc[mi][nf][2], acc[mi][nf][3]);
                }
            }
        }
        grid_bar();

        epilogue(s);
        grid_bar();
    }
}

// ---------------------------------------------------------------------------
// Kernel 3: y = g_h @ W_h2y^T + b_h2y (fp32, small) — unchanged
// ---------------------------------------------------------------------------
__global__ __launch_bounds__(128) void k_out(const float* __restrict__ W,
                                             const float* __restrict__ bias,
                                             float* __restrict__ Y) {
    __shared__ float Hs[16][32];
    __shared__ float Ws[16][32];
    const int K  = DH;
    const int n0 = blockIdx.x * 32;
    const int m0 = blockIdx.y * 32;
    const int t  = threadIdx.x;
    const int nx = t & 15, my = t >> 4;
    const float* __restrict__ Hin = g_h;
    const int lrow = t >> 2;
    const int lkq  = t & 3;

    float2 acc[2][2] = { { make_float2(0.f, 0.f), make_float2(0.f, 0.f) },
                         { make_float2(0.f, 0.f), make_float2(0.f, 0.f) } };

    for (int k0 = 0; k0 < K; k0 += 16) {
        float4 va = *(const float4*)(Hin + (size_t)(m0 + lrow) * K + k0 + lkq * 4);
        float4 vb = *(const float4*)(W   + (size_t)(n0 + lrow) * K + k0 + lkq * 4);
        __syncthreads();
        Hs[lkq*4+0][lrow] = va.x; Hs[lkq*4+1][lrow] = va.y;
        Hs[lkq*4+2][lrow] = va.z; Hs[lkq*4+3][lrow] = va.w;
        Ws[lkq*4+0][lrow] = vb.x; Ws[lkq*4+1][lrow] = vb.y;
        Ws[lkq*4+2][lrow] = vb.z; Ws[lkq*4+3][lrow] = vb.w;
        __syncthreads();

#pragma unroll
        for (int kk = 0; kk < 16; kk++) {
            float4 a = *(const float4*)&Hs[kk][my*4];
            float2 bq = *(const float2*)&Ws[kk][nx*2];
            float2 ap0 = make_float2(a.x, a.y), ap1 = make_float2(a.z, a.w);
            float2 b0  = make_float2(bq.x, bq.x), b1  = make_float2(bq.y, bq.y);
            acc[0][0] = ffma2(ap0, b0, acc[0][0]);
            acc[1][0] = ffma2(ap1, b0, acc[1][0]);
            acc[0][1] = ffma2(ap0, b1, acc[0][1]);
            acc[1][1] = ffma2(ap1, b1, acc[1][1]);
        }
    }

    const int c0 = n0 + nx*2;
    float2 bb = *(const float2*)(bias + c0);
#pragma unroll
    for (int i = 0; i < 4; i++) {
        int m = m0 + my*4 + i;
        float v0 = (i & 1) ? acc[i>>1][0].y : acc[i>>1][0].x;
        float v1 = (i & 1) ? acc[i>>1][1].y : acc[i>>1][1].x;
        float2 o = make_float2(v0 + bb.x, v1 + bb.y);
        *(float2*)(Y + (size_t)m * DOUT + c0) = o;
    }
}

// ---------------------------------------------------------------------------
extern "C" void kernel_launch(void* const* d_in, const int* in_sizes, int n_in,
                              void* d_out, int out_size) {
    (void)in_sizes; (void)n_in; (void)out_size;
    const float* x     = (const float*)d_in[0];
    const float* W_x2h = (const float*)d_in[1];
    const float* b_x2h = (const float*)d_in[2];
    const float* W_h2h = (const float*)d_in[3];
    const float* W_h2y = (const float*)d_in[4];
    const float* b_h2y = (const float*)d_in[5];
    float* y = (float*)d_out;

    // allow 128KB dynamic smem for the persistent kernel
    cudaFuncSetAttribute(k_recur, cudaFuncAttributeMaxDynamicSharedMemorySize,
                         WTILE_U4 * sizeof(uint4));

    // 1) input projection (fp32) + W bf16 hi/lo fragment pack
    k_xh<<<dim3(DH / 128, M1 / 128), 256>>>(x, W_x2h, b_x2h);
    k_packw<<<(NBLK * WTILE_U4) / 256, 256>>>(W_h2h);

    // 2) all 512 recurrence steps in ONE persistent kernel (bf16x3 MMA,
    //    W-in-SMEM persistent, L2-direct A fragments, 16-way split-K)
    k_recur<<<NBLK, NTHR, WTILE_U4 * sizeof(uint4)>>>();

    // 3) output projection
    k_out<<<dim3(DOUT / 32, B_ / 32), 128>>>(W_h2y, b_h2y, y);
}

// round 8
// speedup vs baseline: 5.7063x; 1.2169x over previous
#include <cuda_runtime.h>
#include <cuda_bf16.h>
#include <cstdint>
#include <cstddef>

#define B_   64
#define T_   512
#define DIN  1024
#define DH   2048
#define DOUT 1024
#define M1   (B_ * T_)   // 32768

// Recurrence persistent kernel: 128 blocks = 16 ntiles(128 col) x 8 kchunks(256 K)
#define NBLK    128
#define NTHR    256      // 8 warps: (kh, mh, nh)
#define KGG     128      // k16-groups over DH
#define WTILE_U4 8192    // W tile uint4s per block (128KB)

// ---------------------------------------------------------------------------
// Device globals (allocation-free scratch)
// ---------------------------------------------------------------------------
__device__ float    g_xh[(size_t)M1 * DH];        // 256 MB input projection (fp32)
__device__ float    g_h[B_ * DH];                 // final hidden state (fp32)
// W_h2h bf16 hi/lo packed in m16n8k16 B-fragment order, per block tile:
// uint4 {b0_hi, b1_hi, b0_lo, b1_lo} per (block, kg, nfl, lane)
__device__ uint4    g_Wf[(size_t)NBLK * WTILE_U4];   // 16 MB
// h bf16 hi/lo packed in A-fragment order:
// uint4 {a0,a1,a2,a3} per (kgg, mf, plane, lane)
__device__ uint4    g_hf[KGG * 4 * 2 * 32];          // 512 KB
__device__ float    g_part[16][B_][DH];              // split-K partials, 8 MB
__device__ unsigned g_bar_count;
__device__ unsigned g_bar_phase;

__device__ __forceinline__ float2 ffma2(float2 a, float2 b, float2 c) {
    float2 d;
    asm("fma.rn.f32x2 %0, %1, %2, %3;"
        : "=l"(reinterpret_cast<unsigned long long&>(d))
        : "l"(reinterpret_cast<unsigned long long&>(a)),
          "l"(reinterpret_cast<unsigned long long&>(b)),
          "l"(reinterpret_cast<unsigned long long&>(c)));
    return d;
}

// split (v0, v1) into bf16 hi plane + bf16 lo (residual) plane, packed bf16x2
__device__ __forceinline__ void split2(float v0, float v1,
                                       unsigned& hi, unsigned& lo) {
    __nv_bfloat162 h2 = __floats2bfloat162_rn(v0, v1);
    float2 hf = __bfloat1622float2(h2);
    __nv_bfloat162 l2 = __floats2bfloat162_rn(v0 - hf.x, v1 - hf.y);
    hi = *reinterpret_cast<unsigned*>(&h2);
    lo = *reinterpret_cast<unsigned*>(&l2);
}

__device__ __forceinline__ void mma_bf16(float* c, const uint4& a,
                                         unsigned b0, unsigned b1) {
    asm volatile(
        "mma.sync.aligned.m16n8k16.row.col.f32.bf16.bf16.f32 "
        "{%0,%1,%2,%3}, {%4,%5,%6,%7}, {%8,%9}, {%0,%1,%2,%3};"
        : "+f"(c[0]), "+f"(c[1]), "+f"(c[2]), "+f"(c[3])
        : "r"(a.x), "r"(a.y), "r"(a.z), "r"(a.w), "r"(b0), "r"(b1));
}

// ---------------------------------------------------------------------------
// Kernel 1 (NEW): g_xh = x @ W_x2h^T + b_x2h via bf16x3 tensor-core MMA.
// 128x128 tile, Kc=32 double-buffered fragment-order SMEM, 8 warps (4m x 2n).
// ---------------------------------------------------------------------------
__global__ __launch_bounds__(256) void k_xh_tc(const float* __restrict__ A,
                                               const float* __restrict__ W,
                                               const float* __restrict__ bias) {
    extern __shared__ uint4 smem[];
    uint4* sA = smem;          // [buf][kg][mf 0..7][plane 0..1][lane] : 2048 uint4
    uint4* sB = smem + 2048;   // [buf][kg][nfl 0..15][lane]          : 2048 uint4

    const int tid  = threadIdx.x;
    const int warp = tid >> 5;
    const int lane = tid & 31;
    const int wm = warp >> 1;      // 0..3 : rows wm*32..+31
    const int wn = warp & 1;       // 0..1 : cols wn*64..+63
    const int m0 = blockIdx.y * 128;
    const int n0 = blockIdx.x * 128;
    const int lr = lane >> 2;      // 0..7
    const int lk = (lane & 3) * 2;

    // loader base pointers (thread owns: A item (mf=warp, lane), kg 0/1;
    //                                  W items (nfl=warp, warp+8, lane), kg 0/1)
    const float* Ab = A + (size_t)(m0 + warp * 16 + lr) * DIN + lk;
    const float* Wb0 = W + (size_t)(n0 + warp * 8 + lr) * DIN + lk;
    const float* Wb1 = W + (size_t)(n0 + (warp + 8) * 8 + lr) * DIN + lk;

    float acc[2][8][4];
#pragma unroll
    for (int mi = 0; mi < 2; mi++)
#pragma unroll
        for (int nf = 0; nf < 8; nf++)
#pragma unroll
            for (int i = 0; i < 4; i++) acc[mi][nf][i] = 0.f;

    float2 ax[2][4];        // [kg][{(r,k),(r+8,k),(r,k+8),(r+8,k+8)}]
    float2 wx[2][2][2];     // [kg][nfl half][k01 / k89]

    auto gload = [&](int kc) {
#pragma unroll
        for (int kg = 0; kg < 2; kg++) {
            const float* ap = Ab + kc + kg * 16;
            ax[kg][0] = __ldg((const float2*)ap);
            ax[kg][1] = __ldg((const float2*)(ap + 8 * DIN));
            ax[kg][2] = __ldg((const float2*)(ap + 8));
            ax[kg][3] = __ldg((const float2*)(ap + 8 * DIN + 8));
            const float* wp0 = Wb0 + kc + kg * 16;
            const float* wp1 = Wb1 + kc + kg * 16;
            wx[kg][0][0] = __ldg((const float2*)wp0);
            wx[kg][0][1] = __ldg((const float2*)(wp0 + 8));
            wx[kg][1][0] = __ldg((const float2*)wp1);
            wx[kg][1][1] = __ldg((const float2*)(wp1 + 8));
        }
    };

    auto sstore = [&](int buf) {
#pragma unroll
        for (int kg = 0; kg < 2; kg++) {
            uint4 hi, lo;
            split2(ax[kg][0].x, ax[kg][0].y, hi.x, lo.x);
            split2(ax[kg][1].x, ax[kg][1].y, hi.y, lo.y);
            split2(ax[kg][2].x, ax[kg][2].y, hi.z, lo.z);
            split2(ax[kg][3].x, ax[kg][3].y, hi.w, lo.w);
            sA[buf * 1024 + kg * 512 + warp * 64 + lane]      = hi;
            sA[buf * 1024 + kg * 512 + warp * 64 + 32 + lane] = lo;
            uint4 v0, v1;
            split2(wx[kg][0][0].x, wx[kg][0][0].y, v0.x, v0.z);
            split2(wx[kg][0][1].x, wx[kg][0][1].y, v0.y, v0.w);
            split2(wx[kg][1][0].x, wx[kg][1][0].y, v1.x, v1.z);
            split2(wx[kg][1][1].x, wx[kg][1][1].y, v1.y, v1.w);
            sB[buf * 1024 + kg * 512 + warp * 32 + lane]       = v0;
            sB[buf * 1024 + kg * 512 + (warp + 8) * 32 + lane] = v1;
        }
    };

    auto compute = [&](int buf) {
#pragma unroll
        for (int kg = 0; kg < 2; kg++) {
            const int ab = buf * 1024 + kg * 512;
            uint4 Ah0 = sA[ab + (wm * 2) * 64 + lane];
            uint4 Al0 = sA[ab + (wm * 2) * 64 + 32 + lane];
            uint4 Ah1 = sA[ab + (wm * 2 + 1) * 64 + lane];
            uint4 Al1 = sA[ab + (wm * 2 + 1) * 64 + 32 + lane];
#pragma unroll
            for (int nf = 0; nf < 8; nf++) {
                uint4 w = sB[ab + (wn * 8 + nf) * 32 + lane];
                mma_bf16(acc[0][nf], Ah0, w.x, w.y);   // hi*hi
                mma_bf16(acc[0][nf], Al0, w.x, w.y);   // lo*hi
                mma_bf16(acc[0][nf], Ah0, w.z, w.w);   // hi*lo
                mma_bf16(acc[1][nf], Ah1, w.x, w.y);
                mma_bf16(acc[1][nf], Al1, w.x, w.y);
                mma_bf16(acc[1][nf], Ah1, w.z, w.w);
            }
        }
    };

    gload(0);
    sstore(0);
    __syncthreads();

    for (int kc = 0; kc < DIN; kc += 32) {
        const int buf = (kc >> 5) & 1;
        const bool more = (kc + 32) < DIN;
        if (more) gload(kc + 32);
        compute(buf);
        if (more) sstore(buf ^ 1);
        __syncthreads();
    }

    // epilogue: add bias, store fp32
#pragma unroll
    for (int nf = 0; nf < 8; nf++) {
        const int c = n0 + wn * 64 + nf * 8 + lk;
        float2 bb = __ldg((const float2*)(bias + c));
#pragma unroll
        for (int mi = 0; mi < 2; mi++) {
            const int r = m0 + wm * 32 + mi * 16 + lr;
            *(float2*)(g_xh + (size_t)r * DH + c) =
                make_float2(acc[mi][nf][0] + bb.x, acc[mi][nf][1] + bb.y);
            *(float2*)(g_xh + (size_t)(r + 8) * DH + c) =
                make_float2(acc[mi][nf][2] + bb.x, acc[mi][nf][3] + bb.y);
        }
    }
}

// ---------------------------------------------------------------------------
// Pack W_h2h into bf16 hi/lo B-fragment order (per-block 128KB tiles).
// ---------------------------------------------------------------------------
__global__ void k_packw(const float* __restrict__ W) {
    size_t u = (size_t)blockIdx.x * 256 + threadIdx.x;   // 0 .. 1M-1
    int b    = (int)(u >> 13);
    int r    = (int)(u & 8191);
    int kg   = r >> 9;          // 0..15
    int nfl  = (r >> 5) & 15;   // 0..15
    int lane = r & 31;
    int nt = b >> 3, kch = b & 7;
    int n = nt * 128 + nfl * 8 + (lane >> 2);
    int k = kch * 256 + kg * 16 + (lane & 3) * 2;
    const float* row = W + (size_t)n * DH;
    float w0 = row[k],     w1 = row[k + 1];
    float w2 = row[k + 8], w3 = row[k + 9];
    uint4 v;
    unsigned lo01, lo89;
    split2(w0, w1, v.x, lo01);
    split2(w2, w3, v.y, lo89);
    v.z = lo01;
    v.w = lo89;
    g_Wf[u] = v;
}

// ---------------------------------------------------------------------------
// Persistent recurrence kernel: bf16x3 mma.m16n8k16, W tile persistent in SMEM,
// 8 warps (2/SMSP), A fragments L2-direct, 16-way split-K partials.
// xh loads for the epilogue are hoisted above the MMA phase (DRAM latency hide).
// ---------------------------------------------------------------------------
__global__ __launch_bounds__(NTHR, 1) void k_recur() {
    extern __shared__ uint4 sW[];   // 8192 uint4 = 128 KB

    const int tid  = threadIdx.x;
    const int b    = blockIdx.x;
    const int warp = tid >> 5;
    const int lane = tid & 31;
    const int kh = warp >> 2;          // k-half (0/1): 128 K each
    const int mh = (warp >> 1) & 1;    // m-half: rows mh*32..+31
    const int nh = warp & 1;           // n-half: cols nh*64..+63
    const int nt  = b >> 3;            // ntile 0..15
    const int kch = b & 7;             // kchunk 0..7
    const int pk  = kch * 2 + kh;      // partial buffer index

    // Load persistent W tile into SMEM (once)
    {
        const uint4* wsrc = g_Wf + (size_t)b * WTILE_U4;
        for (int i = tid; i < WTILE_U4; i += NTHR) sW[i] = __ldg(wsrc + i);
    }

    // replay-safe grid barrier
    unsigned bar_base;
    asm volatile("ld.acquire.gpu.global.u32 %0, [%1];"
                 : "=r"(bar_base) : "l"(&g_bar_phase));
    unsigned bar_t = 0;

    auto grid_bar = [&]() {
        bar_t++;
        __syncthreads();
        __threadfence();
        if (tid == 0) {
            unsigned arr = atomicAdd(&g_bar_count, 1);
            if (arr == NBLK - 1) {
                atomicExch(&g_bar_count, 0);
                __threadfence();
                atomicAdd(&g_bar_phase, 1);
            } else {
                unsigned p;
                do {
                    __nanosleep(32);
                    asm volatile("ld.acquire.gpu.global.u32 %0, [%1];"
                                 : "=r"(p) : "l"(&g_bar_phase));
                } while (p - bar_base < bar_t);
            }
        }
        __syncthreads();
    };

    // Epilogue mapping: block b owns kgg = b (16 h-columns), threads 0..127
    const int elane = tid & 31;
    const int emf   = (tid >> 5) & 3;
    const int er    = emf * 16 + (elane >> 2);       // row (and +8)
    const int ek0   = b * 16 + (elane & 3) * 2;      // col (and +1, +8, +9)
    uint4* hf_hi = g_hf + ((b * 4 + emf) * 2 + 0) * 32 + elane;
    uint4* hf_lo = g_hf + ((b * 4 + emf) * 2 + 1) * 32 + elane;

    // preloaded xh values for epilogue of step s (loads xh_{s-1})
    auto xh_load = [&](int s, float2& v00, float2& v01, float2& v10, float2& v11) {
        const float* x0 = &g_xh[((size_t)er * T_ + (s - 1)) * DH + ek0];
        const float* x1 = &g_xh[((size_t)(er + 8) * T_ + (s - 1)) * DH + ek0];
        v00 = __ldg((const float2*)x0);
        v01 = __ldg((const float2*)(x0 + 8));
        v10 = __ldg((const float2*)x1);
        v11 = __ldg((const float2*)(x1 + 8));
    };

    auto epilogue = [&](int s, float2 v00, float2 v01, float2 v10, float2 v11,
                        bool addp) {
        if (addp) {
#pragma unroll
            for (int p = 0; p < 16; p++) {
                const float* pb = &g_part[p][0][0];
                const float* p0 = pb + (size_t)er * DH + ek0;
                const float* p1 = pb + (size_t)(er + 8) * DH + ek0;
                float2 q;
                q = __ldcg((const float2*)p0);       v00.x += q.x; v00.y += q.y;
                q = __ldcg((const float2*)(p0 + 8)); v01.x += q.x; v01.y += q.y;
                q = __ldcg((const float2*)p1);       v10.x += q.x; v10.y += q.y;
                q = __ldcg((const float2*)(p1 + 8)); v11.x += q.x; v11.y += q.y;
            }
        }
        v00.x = fmaxf(v00.x, 0.f); v00.y = fmaxf(v00.y, 0.f);
        v01.x = fmaxf(v01.x, 0.f); v01.y = fmaxf(v01.y, 0.f);
        v10.x = fmaxf(v10.x, 0.f); v10.y = fmaxf(v10.y, 0.f);
        v11.x = fmaxf(v11.x, 0.f); v11.y = fmaxf(v11.y, 0.f);
        uint4 hi, lo;
        split2(v00.x, v00.y, hi.x, lo.x);   // a0: (r,   k0,k0+1)
        split2(v10.x, v10.y, hi.y, lo.y);   // a1: (r+8, k0,k0+1)
        split2(v01.x, v01.y, hi.z, lo.z);   // a2: (r,   k0+8,k0+9)
        split2(v11.x, v11.y, hi.w, lo.w);   // a3: (r+8, k0+8,k0+9)
        *hf_hi = hi;
        *hf_lo = lo;
        if (s == T_) {
            *(float2*)&g_h[(size_t)er * DH + ek0]           = v00;
            *(float2*)&g_h[(size_t)er * DH + ek0 + 8]       = v01;
            *(float2*)&g_h[(size_t)(er + 8) * DH + ek0]     = v10;
            *(float2*)&g_h[(size_t)(er + 8) * DH + ek0 + 8] = v11;
        }
    };

    if (tid < 128) {   // h_1 = relu(xh_0)
        float2 v00, v01, v10, v11;
        xh_load(1, v00, v01, v10, v11);
        epilogue(1, v00, v01, v10, v11, false);
    }
    grid_bar();

    const int kggbase = kch * 16 + kh * 8;

    for (int s = 2; s <= T_; s++) {
        // hoisted epilogue xh loads for this step (hide DRAM latency under MMA)
        float2 pv00, pv01, pv10, pv11;
        if (tid < 128) xh_load(s, pv00, pv01, pv10, pv11);

        // ---- MMA phase: partial[pk] = h_{s-1}[:, kslice] @ W[ntile, kslice]^T
        float acc[2][8][4];
#pragma unroll
        for (int mi = 0; mi < 2; mi++)
#pragma unroll
            for (int nf = 0; nf < 8; nf++)
#pragma unroll
                for (int i = 0; i < 4; i++) acc[mi][nf][i] = 0.f;

        // prefetch kg=0 A fragments
        const uint4* ab0 = g_hf + ((kggbase * 4 + mh * 2) * 2) * 32 + lane;
        uint4 A0h = __ldcg(ab0);
        uint4 A0l = __ldcg(ab0 + 32);
        uint4 A1h = __ldcg(ab0 + 64);
        uint4 A1l = __ldcg(ab0 + 96);

#pragma unroll
        for (int kg = 0; kg < 8; kg++) {
            uint4 N0h, N0l, N1h, N1l;
            if (kg < 7) {
                const uint4* ab =
                    g_hf + (((kggbase + kg + 1) * 4 + mh * 2) * 2) * 32 + lane;
                N0h = __ldcg(ab);
                N0l = __ldcg(ab + 32);
                N1h = __ldcg(ab + 64);
                N1l = __ldcg(ab + 96);
            }
            const int wb = ((kh * 8 + kg) * 16 + nh * 8) * 32 + lane;
#pragma unroll
            for (int nf = 0; nf < 8; nf++) {
                uint4 w = sW[wb + nf * 32];
                mma_bf16(acc[0][nf], A0h, w.x, w.y);   // hi*hi
                mma_bf16(acc[0][nf], A0l, w.x, w.y);   // lo*hi
                mma_bf16(acc[0][nf], A0h, w.z, w.w);   // hi*lo
                mma_bf16(acc[1][nf], A1h, w.x, w.y);
                mma_bf16(acc[1][nf], A1l, w.x, w.y);
                mma_bf16(acc[1][nf], A1h, w.z, w.w);
            }
            if (kg < 7) { A0h = N0h; A0l = N0l; A1h = N1h; A1l = N1l; }
        }

        // write split-K partials (fp32)
        {
            float* pb = &g_part[pk][0][0];
            const int cb = nt * 128 + nh * 64 + (lane & 3) * 2;
#pragma unroll
            for (int mi = 0; mi < 2; mi++) {
                const int r = mh * 32 + mi * 16 + (lane >> 2);
#pragma unroll
                for (int nf = 0; nf < 8; nf++) {
                    const int c = cb + nf * 8;
                    *(float2*)&pb[(size_t)r * DH + c] =
                        make_float2(acc[mi][nf][0], acc[mi][nf][1]);
                    *(float2*)&pb[(size_t)(r + 8) * DH + c] =
                        make_float2(acc[mi][nf][2], acc[mi][nf][3]);
                }
            }
        }
        grid_bar();

        if (tid < 128) epilogue(s, pv00, pv01, pv10, pv11, true);
        grid_bar();
    }
}

// ---------------------------------------------------------------------------
// Kernel 3: y = g_h @ W_h2y^T + b_h2y, 8-way split-K + atomicAdd.
// ---------------------------------------------------------------------------
__global__ void k_out_init(const float* __restrict__ bias, float* __restrict__ Y) {
    int idx = blockIdx.x * 256 + threadIdx.x;
    Y[idx] = bias[idx & (DOUT - 1)];
}

__global__ __launch_bounds__(128) void k_out(const float* __restrict__ W,
                                             float* __restrict__ Y) {
    __shared__ float Hs[16][32];
    __shared__ float Ws[16][32];
    const int n0  = blockIdx.x * 32;
    const int m0  = blockIdx.y * 32;
    const int kc0 = blockIdx.z * (DH / 8);
    const int t   = threadIdx.x;
    const int nx = t & 15, my = t >> 4;
    const float* __restrict__ Hin = g_h;
    const int lrow = t >> 2;
    const int lkq  = t & 3;

    float2 acc[2][2] = { { make_float2(0.f, 0.f), make_float2(0.f, 0.f) },
                         { make_float2(0.f, 0.f), make_float2(0.f, 0.f) } };

    for (int k0 = kc0; k0 < kc0 + DH / 8; k0 += 16) {
        float4 va = *(const float4*)(Hin + (size_t)(m0 + lrow) * DH + k0 + lkq * 4);
        float4 vb = *(const float4*)(W   + (size_t)(n0 + lrow) * DH + k0 + lkq * 4);
        __syncthreads();
        Hs[lkq*4+0][lrow] = va.x; Hs[lkq*4+1][lrow] = va.y;
        Hs[lkq*4+2][lrow] = va.z; Hs[lkq*4+3][lrow] = va.w;
        Ws[lkq*4+0][lrow] = vb.x; Ws[lkq*4+1][lrow] = vb.y;
        Ws[lkq*4+2][lrow] = vb.z; Ws[lkq*4+3][lrow] = vb.w;
        __syncthreads();

#pragma unroll
        for (int kk = 0; kk < 16; kk++) {
            float4 a = *(const float4*)&Hs[kk][my*4];
            float2 bq = *(const float2*)&Ws[kk][nx*2];
            float2 ap0 = make_float2(a.x, a.y), ap1 = make_float2(a.z, a.w);
            float2 b0  = make_float2(bq.x, bq.x), b1  = make_float2(bq.y, bq.y);
            acc[0][0] = ffma2(ap0, b0, acc[0][0]);
            acc[1][0] = ffma2(ap1, b0, acc[1][0]);
            acc[0][1] = ffma2(ap0, b1, acc[0][1]);
            acc[1][1] = ffma2(ap1, b1, acc[1][1]);
        }
    }

    const int c0 = n0 + nx*2;
#pragma unroll
    for (int i = 0; i < 4; i++) {
        int m = m0 + my*4 + i;
        float v0 = (i & 1) ? acc[i>>1][0].y : acc[i>>1][0].x;
        float v1 = (i & 1) ? acc[i>>1][1].y : acc[i>>1][1].x;
        atomicAdd(&Y[(size_t)m * DOUT + c0],     v0);
        atomicAdd(&Y[(size_t)m * DOUT + c0 + 1], v1);
    }
}

// ---------------------------------------------------------------------------
extern "C" void kernel_launch(void* const* d_in, const int* in_sizes, int n_in,
                              void* d_out, int out_size) {
    (void)in_sizes; (void)n_in; (void)out_size;
    const float* x     = (const float*)d_in[0];
    const float* W_x2h = (const float*)d_in[1];
    const float* b_x2h = (const float*)d_in[2];
    const float* W_h2h = (const float*)d_in[3];
    const float* W_h2y = (const float*)d_in[4];
    const float* b_h2y = (const float*)d_in[5];
    float* y = (float*)d_out;

    cudaFuncSetAttribute(k_recur, cudaFuncAttributeMaxDynamicSharedMemorySize,
                         WTILE_U4 * sizeof(uint4));
    cudaFuncSetAttribute(k_xh_tc, cudaFuncAttributeMaxDynamicSharedMemorySize,
                         65536);

    // 1) input projection (bf16x3 tensor cores) + W bf16 hi/lo fragment pack
    k_xh_tc<<<dim3(DH / 128, M1 / 128), 256, 65536>>>(x, W_x2h, b_x2h);
    k_packw<<<(NBLK * WTILE_U4) / 256, 256>>>(W_h2h);

    // 2) all 512 recurrence steps in ONE persistent kernel (bf16x3 MMA,
    //    W-in-SMEM persistent, L2-direct A fragments, 16-way split-K)
    k_recur<<<NBLK, NTHR, WTILE_U4 * sizeof(uint4)>>>();

    // 3) output projection (split-K + atomics over bias-initialized Y)
    k_out_init<<<(B_ * DOUT) / 256, 256>>>(b_h2y, y);
    k_out<<<dim3(DOUT / 32, B_ / 32, 8), 128>>>(W_h2y, y);
}

// round 9
// speedup vs baseline: 5.7069x; 1.0001x over previous
#include <cuda_runtime.h>
#include <cuda_bf16.h>
#include <cstdint>
#include <cstddef>

#define B_   64
#define T_   512
#define DIN  1024
#define DH   2048
#define DOUT 1024
#define M1   (B_ * T_)   // 32768

// Recurrence persistent kernel: 128 blocks = 16 ntiles(128 col) x 8 kchunks(256 K)
#define NBLK    128
#define NTHR    256      // 8 warps: (kh, mh, nh)
#define KGG     128      // k16-groups over DH
#define WTILE_U4 8192    // W tile uint4s per block (128KB)

// ---------------------------------------------------------------------------
// Device globals (allocation-free scratch)
// ---------------------------------------------------------------------------
__device__ float    g_xh[(size_t)M1 * DH];        // 256 MB input projection (fp32)
__device__ float    g_h[B_ * DH];                 // final hidden state (fp32)
// W_h2h bf16 hi/lo packed in m16n8k16 B-fragment order, per block tile:
// uint4 {b0_hi, b1_hi, b0_lo, b1_lo} per (block, kg, nfl, lane)
__device__ uint4    g_Wf[(size_t)NBLK * WTILE_U4];   // 16 MB
// h bf16 hi/lo packed in A-fragment order:
// uint4 {a0,a1,a2,a3} per (kgg, mf, plane, lane)
__device__ uint4    g_hf[KGG * 4 * 2 * 32];          // 512 KB
__device__ float    g_part[16][B_][DH];              // split-K partials, 8 MB
__device__ unsigned g_bar_count;
__device__ unsigned g_bar_phase;

__device__ __forceinline__ float2 ffma2(float2 a, float2 b, float2 c) {
    float2 d;
    asm("fma.rn.f32x2 %0, %1, %2, %3;"
        : "=l"(reinterpret_cast<unsigned long long&>(d))
        : "l"(reinterpret_cast<unsigned long long&>(a)),
          "l"(reinterpret_cast<unsigned long long&>(b)),
          "l"(reinterpret_cast<unsigned long long&>(c)));
    return d;
}

// split (v0, v1) into bf16 hi plane + bf16 lo (residual) plane, packed bf16x2
__device__ __forceinline__ void split2(float v0, float v1,
                                       unsigned& hi, unsigned& lo) {
    __nv_bfloat162 h2 = __floats2bfloat162_rn(v0, v1);
    float2 hf = __bfloat1622float2(h2);
    __nv_bfloat162 l2 = __floats2bfloat162_rn(v0 - hf.x, v1 - hf.y);
    hi = *reinterpret_cast<unsigned*>(&h2);
    lo = *reinterpret_cast<unsigned*>(&l2);
}

__device__ __forceinline__ void mma_bf16(float* c, const uint4& a,
                                         unsigned b0, unsigned b1) {
    asm volatile(
        "mma.sync.aligned.m16n8k16.row.col.f32.bf16.bf16.f32 "
        "{%0,%1,%2,%3}, {%4,%5,%6,%7}, {%8,%9}, {%0,%1,%2,%3};"
        : "+f"(c[0]), "+f"(c[1]), "+f"(c[2]), "+f"(c[3])
        : "r"(a.x), "r"(a.y), "r"(a.z), "r"(a.w), "r"(b0), "r"(b1));
}

// ---------------------------------------------------------------------------
// Kernel 1 (NEW): g_xh = x @ W_x2h^T + b_x2h via bf16x3 tensor-core MMA.
// 128x128 tile, Kc=32 double-buffered fragment-order SMEM, 8 warps (4m x 2n).
// ---------------------------------------------------------------------------
__global__ __launch_bounds__(256) void k_xh_tc(const float* __restrict__ A,
                                               const float* __restrict__ W,
                                               const float* __restrict__ bias) {
    extern __shared__ uint4 smem[];
    uint4* sA = smem;          // [buf][kg][mf 0..7][plane 0..1][lane] : 2048 uint4
    uint4* sB = smem + 2048;   // [buf][kg][nfl 0..15][lane]          : 2048 uint4

    const int tid  = threadIdx.x;
    const int warp = tid >> 5;
    const int lane = tid & 31;
    const int wm = warp >> 1;      // 0..3 : rows wm*32..+31
    const int wn = warp & 1;       // 0..1 : cols wn*64..+63
    const int m0 = blockIdx.y * 128;
    const int n0 = blockIdx.x * 128;
    const int lr = lane >> 2;      // 0..7
    const int lk = (lane & 3) * 2;

    // loader base pointers (thread owns: A item (mf=warp, lane), kg 0/1;
    //                                  W items (nfl=warp, warp+8, lane), kg 0/1)
    const float* Ab = A + (size_t)(m0 + warp * 16 + lr) * DIN + lk;
    const float* Wb0 = W + (size_t)(n0 + warp * 8 + lr) * DIN + lk;
    const float* Wb1 = W + (size_t)(n0 + (warp + 8) * 8 + lr) * DIN + lk;

    float acc[2][8][4];
#pragma unroll
    for (int mi = 0; mi < 2; mi++)
#pragma unroll
        for (int nf = 0; nf < 8; nf++)
#pragma unroll
            for (int i = 0; i < 4; i++) acc[mi][nf][i] = 0.f;

    float2 ax[2][4];        // [kg][{(r,k),(r+8,k),(r,k+8),(r+8,k+8)}]
    float2 wx[2][2][2];     // [kg][nfl half][k01 / k89]

    auto gload = [&](int kc) {
#pragma unroll
        for (int kg = 0; kg < 2; kg++) {
            const float* ap = Ab + kc + kg * 16;
            ax[kg][0] = __ldg((const float2*)ap);
            ax[kg][1] = __ldg((const float2*)(ap + 8 * DIN));
            ax[kg][2] = __ldg((const float2*)(ap + 8));
            ax[kg][3] = __ldg((const float2*)(ap + 8 * DIN + 8));
            const float* wp0 = Wb0 + kc + kg * 16;
            const float* wp1 = Wb1 + kc + kg * 16;
            wx[kg][0][0] = __ldg((const float2*)wp0);
            wx[kg][0][1] = __ldg((const float2*)(wp0 + 8));
            wx[kg][1][0] = __ldg((const float2*)wp1);
            wx[kg][1][1] = __ldg((const float2*)(wp1 + 8));
        }
    };

    auto sstore = [&](int buf) {
#pragma unroll
        for (int kg = 0; kg < 2; kg++) {
            uint4 hi, lo;
            split2(ax[kg][0].x, ax[kg][0].y, hi.x, lo.x);
            split2(ax[kg][1].x, ax[kg][1].y, hi.y, lo.y);
            split2(ax[kg][2].x, ax[kg][2].y, hi.z, lo.z);
            split2(ax[kg][3].x, ax[kg][3].y, hi.w, lo.w);
            sA[buf * 1024 + kg * 512 + warp * 64 + lane]      = hi;
            sA[buf * 1024 + kg * 512 + warp * 64 + 32 + lane] = lo;
            uint4 v0, v1;
            split2(wx[kg][0][0].x, wx[kg][0][0].y, v0.x, v0.z);
            split2(wx[kg][0][1].x, wx[kg][0][1].y, v0.y, v0.w);
            split2(wx[kg][1][0].x, wx[kg][1][0].y, v1.x, v1.z);
            split2(wx[kg][1][1].x, wx[kg][1][1].y, v1.y, v1.w);
            sB[buf * 1024 + kg * 512 + warp * 32 + lane]       = v0;
            sB[buf * 1024 + kg * 512 + (warp + 8) * 32 + lane] = v1;
        }
    };

    auto compute = [&](int buf) {
#pragma unroll
        for (int kg = 0; kg < 2; kg++) {
            const int ab = buf * 1024 + kg * 512;
            uint4 Ah0 = sA[ab + (wm * 2) * 64 + lane];
            uint4 Al0 = sA[ab + (wm * 2) * 64 + 32 + lane];
            uint4 Ah1 = sA[ab + (wm * 2 + 1) * 64 + lane];
            uint4 Al1 = sA[ab + (wm * 2 + 1) * 64 + 32 + lane];
#pragma unroll
            for (int nf = 0; nf < 8; nf++) {
                uint4 w = sB[ab + (wn * 8 + nf) * 32 + lane];
                mma_bf16(acc[0][nf], Ah0, w.x, w.y);   // hi*hi
                mma_bf16(acc[0][nf], Al0, w.x, w.y);   // lo*hi
                mma_bf16(acc[0][nf], Ah0, w.z, w.w);   // hi*lo
                mma_bf16(acc[1][nf], Ah1, w.x, w.y);
                mma_bf16(acc[1][nf], Al1, w.x, w.y);
                mma_bf16(acc[1][nf], Ah1, w.z, w.w);
            }
        }
    };

    gload(0);
    sstore(0);
    __syncthreads();

    for (int kc = 0; kc < DIN; kc += 32) {
        const int buf = (kc >> 5) & 1;
        const bool more = (kc + 32) < DIN;
        if (more) gload(kc + 32);
        compute(buf);
        if (more) sstore(buf ^ 1);
        __syncthreads();
    }

    // epilogue: add bias, store fp32
#pragma unroll
    for (int nf = 0; nf < 8; nf++) {
        const int c = n0 + wn * 64 + nf * 8 + lk;
        float2 bb = __ldg((const float2*)(bias + c));
#pragma unroll
        for (int mi = 0; mi < 2; mi++) {
            const int r = m0 + wm * 32 + mi * 16 + lr;
            *(float2*)(g_xh + (size_t)r * DH + c) =
                make_float2(acc[mi][nf][0] + bb.x, acc[mi][nf][1] + bb.y);
            *(float2*)(g_xh + (size_t)(r + 8) * DH + c) =
                make_float2(acc[mi][nf][2] + bb.x, acc[mi][nf][3] + bb.y);
        }
    }
}

// ---------------------------------------------------------------------------
// Pack W_h2h into bf16 hi/lo B-fragment order (per-block 128KB tiles).
// ---------------------------------------------------------------------------
__global__ void k_packw(const float* __restrict__ W) {
    size_t u = (size_t)blockIdx.x * 256 + threadIdx.x;   // 0 .. 1M-1
    int b    = (int)(u >> 13);
    int r    = (int)(u & 8191);
    int kg   = r >> 9;          // 0..15
    int nfl  = (r >> 5) & 15;   // 0..15
    int lane = r & 31;
    int nt = b >> 3, kch = b & 7;
    int n = nt * 128 + nfl * 8 + (lane >> 2);
    int k = kch * 256 + kg * 16 + (lane & 3) * 2;
    const float* row = W + (size_t)n * DH;
    float w0 = row[k],     w1 = row[k + 1];
    float w2 = row[k + 8], w3 = row[k + 9];
    uint4 v;
    unsigned lo01, lo89;
    split2(w0, w1, v.x, lo01);
    split2(w2, w3, v.y, lo89);
    v.z = lo01;
    v.w = lo89;
    g_Wf[u] = v;
}

// ---------------------------------------------------------------------------
// Persistent recurrence kernel: bf16x3 mma.m16n8k16, W tile persistent in SMEM,
// 8 warps (2/SMSP), A fragments L2-direct, 16-way split-K partials.
// xh loads for the epilogue are hoisted above the MMA phase (DRAM latency hide).
// ---------------------------------------------------------------------------
__global__ __launch_bounds__(NTHR, 1) void k_recur() {
    extern __shared__ uint4 sW[];   // 8192 uint4 = 128 KB

    const int tid  = threadIdx.x;
    const int b    = blockIdx.x;
    const int warp = tid >> 5;
    const int lane = tid & 31;
    const int kh = warp >> 2;          // k-half (0/1): 128 K each
    const int mh = (warp >> 1) & 1;    // m-half: rows mh*32..+31
    const int nh = warp & 1;           // n-half: cols nh*64..+63
    const int nt  = b >> 3;            // ntile 0..15
    const int kch = b & 7;             // kchunk 0..7
    const int pk  = kch * 2 + kh;      // partial buffer index

    // Load persistent W tile into SMEM (once)
    {
        const uint4* wsrc = g_Wf + (size_t)b * WTILE_U4;
        for (int i = tid; i < WTILE_U4; i += NTHR) sW[i] = __ldg(wsrc + i);
    }

    // replay-safe grid barrier
    unsigned bar_base;
    asm volatile("ld.acquire.gpu.global.u32 %0, [%1];"
                 : "=r"(bar_base) : "l"(&g_bar_phase));
    unsigned bar_t = 0;

    auto grid_bar = [&]() {
        bar_t++;
        __syncthreads();
        __threadfence();
        if (tid == 0) {
            unsigned arr = atomicAdd(&g_bar_count, 1);
            if (arr == NBLK - 1) {
                atomicExch(&g_bar_count, 0);
                __threadfence();
                atomicAdd(&g_bar_phase, 1);
            } else {
                unsigned p;
                do {
                    __nanosleep(32);
                    asm volatile("ld.acquire.gpu.global.u32 %0, [%1];"
                                 : "=r"(p) : "l"(&g_bar_phase));
                } while (p - bar_base < bar_t);
            }
        }
        __syncthreads();
    };

    // Epilogue mapping: block b owns kgg = b (16 h-columns), threads 0..127
    const int elane = tid & 31;
    const int emf   = (tid >> 5) & 3;
    const int er    = emf * 16 + (elane >> 2);       // row (and +8)
    const int ek0   = b * 16 + (elane & 3) * 2;      // col (and +1, +8, +9)
    uint4* hf_hi = g_hf + ((b * 4 + emf) * 2 + 0) * 32 + elane;
    uint4* hf_lo = g_hf + ((b * 4 + emf) * 2 + 1) * 32 + elane;

    // preloaded xh values for epilogue of step s (loads xh_{s-1})
    auto xh_load = [&](int s, float2& v00, float2& v01, float2& v10, float2& v11) {
        const float* x0 = &g_xh[((size_t)er * T_ + (s - 1)) * DH + ek0];
        const float* x1 = &g_xh[((size_t)(er + 8) * T_ + (s - 1)) * DH + ek0];
        v00 = __ldg((const float2*)x0);
        v01 = __ldg((const float2*)(x0 + 8));
        v10 = __ldg((const float2*)x1);
        v11 = __ldg((const float2*)(x1 + 8));
    };

    auto epilogue = [&](int s, float2 v00, float2 v01, float2 v10, float2 v11,
                        bool addp) {
        if (addp) {
#pragma unroll
            for (int p = 0; p < 16; p++) {
                const float* pb = &g_part[p][0][0];
                const float* p0 = pb + (size_t)er * DH + ek0;
                const float* p1 = pb + (size_t)(er + 8) * DH + ek0;
                float2 q;
                q = __ldcg((const float2*)p0);       v00.x += q.x; v00.y += q.y;
                q = __ldcg((const float2*)(p0 + 8)); v01.x += q.x; v01.y += q.y;
                q = __ldcg((const float2*)p1);       v10.x += q.x; v10.y += q.y;
                q = __ldcg((const float2*)(p1 + 8)); v11.x += q.x; v11.y += q.y;
            }
        }
        v00.x = fmaxf(v00.x, 0.f); v00.y = fmaxf(v00.y, 0.f);
        v01.x = fmaxf(v01.x, 0.f); v01.y = fmaxf(v01.y, 0.f);
        v10.x = fmaxf(v10.x, 0.f); v10.y = fmaxf(v10.y, 0.f);
        v11.x = fmaxf(v11.x, 0.f); v11.y = fmaxf(v11.y, 0.f);
        uint4 hi, lo;
        split2(v00.x, v00.y, hi.x, lo.x);   // a0: (r,   k0,k0+1)
        split2(v10.x, v10.y, hi.y, lo.y);   // a1: (r+8, k0,k0+1)
        split2(v01.x, v01.y, hi.z, lo.z);   // a2: (r,   k0+8,k0+9)
        split2(v11.x, v11.y, hi.w, lo.w);   // a3: (r+8, k0+8,k0+9)
        *hf_hi = hi;
        *hf_lo = lo;
        if (s == T_) {
            *(float2*)&g_h[(size_t)er * DH + ek0]           = v00;
            *(float2*)&g_h[(size_t)er * DH + ek0 + 8]       = v01;
            *(float2*)&g_h[(size_t)(er + 8) * DH + ek0]     = v10;
            *(float2*)&g_h[(size_t)(er + 8) * DH + ek0 + 8] = v11;
        }
    };

    if (tid < 128) {   // h_1 = relu(xh_0)
        float2 v00, v01, v10, v11;
        xh_load(1, v00, v01, v10, v11);
        epilogue(1, v00, v01, v10, v11, false);
    }
    grid_bar();

    const int kggbase = kch * 16 + kh * 8;

    for (int s = 2; s <= T_; s++) {
        // hoisted epilogue xh loads for this step (hide DRAM latency under MMA)
        float2 pv00, pv01, pv10, pv11;
        if (tid < 128) xh_load(s, pv00, pv01, pv10, pv11);

        // ---- MMA phase: partial[pk] = h_{s-1}[:, kslice] @ W[ntile, kslice]^T
        float acc[2][8][4];
#pragma unroll
        for (int mi = 0; mi < 2; mi++)
#pragma unroll
            for (int nf = 0; nf < 8; nf++)
#pragma unroll
                for (int i = 0; i < 4; i++) acc[mi][nf][i] = 0.f;

        // prefetch kg=0 A fragments
        const uint4* ab0 = g_hf + ((kggbase * 4 + mh * 2) * 2) * 32 + lane;
        uint4 A0h = __ldcg(ab0);
        uint4 A0l = __ldcg(ab0 + 32);
        uint4 A1h = __ldcg(ab0 + 64);
        uint4 A1l = __ldcg(ab0 + 96);

#pragma unroll
        for (int kg = 0; kg < 8; kg++) {
            uint4 N0h, N0l, N1h, N1l;
            if (kg < 7) {
                const uint4* ab =
                    g_hf + (((kggbase + kg + 1) * 4 + mh * 2) * 2) * 32 + lane;
                N0h = __ldcg(ab);
                N0l = __ldcg(ab + 32);
                N1h = __ldcg(ab + 64);
                N1l = __ldcg(ab + 96);
            }
            const int wb = ((kh * 8 + kg) * 16 + nh * 8) * 32 + lane;
#pragma unroll
            for (int nf = 0; nf < 8; nf++) {
                uint4 w = sW[wb + nf * 32];
                mma_bf16(acc[0][nf], A0h, w.x, w.y);   // hi*hi
                mma_bf16(acc[0][nf], A0l, w.x, w.y);   // lo*hi
                mma_bf16(acc[0][nf], A0h, w.z, w.w);   // hi*lo
                mma_bf16(acc[1][nf], A1h, w.x, w.y);
                mma_bf16(acc[1][nf], A1l, w.x, w.y);
                mma_bf16(acc[1][nf], A1h, w.z, w.w);
            }
            if (kg < 7) { A0h = N0h; A0l = N0l; A1h = N1h; A1l = N1l; }
        }

        // write split-K partials (fp32)
        {
            float* pb = &g_part[pk][0][0];
            const int cb = nt * 128 + nh * 64 + (lane & 3) * 2;
#pragma unroll
            for (int mi = 0; mi < 2; mi++) {
                const int r = mh * 32 + mi * 16 + (lane >> 2);
#pragma unroll
                for (int nf = 0; nf < 8; nf++) {
                    const int c = cb + nf * 8;
                    *(float2*)&pb[(size_t)r * DH + c] =
                        make_float2(acc[mi][nf][0], acc[mi][nf][1]);
                    *(float2*)&pb[(size_t)(r + 8) * DH + c] =
                        make_float2(acc[mi][nf][2], acc[mi][nf][3]);
                }
            }
        }
        grid_bar();

        if (tid < 128) epilogue(s, pv00, pv01, pv10, pv11, true);
        grid_bar();
    }
}

// ---------------------------------------------------------------------------
// Kernel 3: y = g_h @ W_h2y^T + b_h2y, 8-way split-K + atomicAdd.
// ---------------------------------------------------------------------------
__global__ void k_out_init(const float* __restrict__ bias, float* __restrict__ Y) {
    int idx = blockIdx.x * 256 + threadIdx.x;
    Y[idx] = bias[idx & (DOUT - 1)];
}

__global__ __launch_bounds__(128) void k_out(const float* __restrict__ W,
                                             float* __restrict__ Y) {
    __shared__ float Hs[16][32];
    __shared__ float Ws[16][32];
    const int n0  = blockIdx.x * 32;
    const int m0  = blockIdx.y * 32;
    const int kc0 = blockIdx.z * (DH / 8);
    const int t   = threadIdx.x;
    const int nx = t & 15, my = t >> 4;
    const float* __restrict__ Hin = g_h;
    const int lrow = t >> 2;
    const int lkq  = t & 3;

    float2 acc[2][2] = { { make_float2(0.f, 0.f), make_float2(0.f, 0.f) },
                         { make_float2(0.f, 0.f), make_float2(0.f, 0.f) } };

    for (int k0 = kc0; k0 < kc0 + DH / 8; k0 += 16) {
        float4 va = *(const float4*)(Hin + (size_t)(m0 + lrow) * DH + k0 + lkq * 4);
        float4 vb = *(const float4*)(W   + (size_t)(n0 + lrow) * DH + k0 + lkq * 4);
        __syncthreads();
        Hs[lkq*4+0][lrow] = va.x; Hs[lkq*4+1][lrow] = va.y;
        Hs[lkq*4+2][lrow] = va.z; Hs[lkq*4+3][lrow] = va.w;
        Ws[lkq*4+0][lrow] = vb.x; Ws[lkq*4+1][lrow] = vb.y;
        Ws[lkq*4+2][lrow] = vb.z; Ws[lkq*4+3][lrow] = vb.w;
        __syncthreads();

#pragma unroll
        for (int kk = 0; kk < 16; kk++) {
            float4 a = *(const float4*)&Hs[kk][my*4];
            float2 bq = *(const float2*)&Ws[kk][nx*2];
            float2 ap0 = make_float2(a.x, a.y), ap1 = make_float2(a.z, a.w);
            float2 b0  = make_float2(bq.x, bq.x), b1  = make_float2(bq.y, bq.y);
            acc[0][0] = ffma2(ap0, b0, acc[0][0]);
            acc[1][0] = ffma2(ap1, b0, acc[1][0]);
            acc[0][1] = ffma2(ap0, b1, acc[0][1]);
            acc[1][1] = ffma2(ap1, b1, acc[1][1]);
        }
    }

    const int c0 = n0 + nx*2;
#pragma unroll
    for (int i = 0; i < 4; i++) {
        int m = m0 + my*4 + i;
        float v0 = (i & 1) ? acc[i>>1][0].y : acc[i>>1][0].x;
        float v1 = (i & 1) ? acc[i>>1][1].y : acc[i>>1][1].x;
        atomicAdd(&Y[(size_t)m * DOUT + c0],     v0);
        atomicAdd(&Y[(size_t)m * DOUT + c0 + 1], v1);
    }
}

// ---------------------------------------------------------------------------
extern "C" void kernel_launch(void* const* d_in, const int* in_sizes, int n_in,
                              void* d_out, int out_size) {
    (void)in_sizes; (void)n_in; (void)out_size;
    const float* x     = (const float*)d_in[0];
    const float* W_x2h = (const float*)d_in[1];
    const float* b_x2h = (const float*)d_in[2];
    const float* W_h2h = (const float*)d_in[3];
    const float* W_h2y = (const float*)d_in[4];
    const float* b_h2y = (const float*)d_in[5];
    float* y = (float*)d_out;

    cudaFuncSetAttribute(k_recur, cudaFuncAttributeMaxDynamicSharedMemorySize,
                         WTILE_U4 * sizeof(uint4));
    cudaFuncSetAttribute(k_xh_tc, cudaFuncAttributeMaxDynamicSharedMemorySize,
                         65536);

    // 1) input projection (bf16x3 tensor cores) + W bf16 hi/lo fragment pack
    k_xh_tc<<<dim3(DH / 128, M1 / 128), 256, 65536>>>(x, W_x2h, b_x2h);
    k_packw<<<(NBLK * WTILE_U4) / 256, 256>>>(W_h2h);

    // 2) all 512 recurrence steps in ONE persistent kernel (bf16x3 MMA,
    //    W-in-SMEM persistent, L2-direct A fragments, 16-way split-K)
    k_recur<<<NBLK, NTHR, WTILE_U4 * sizeof(uint4)>>>();

    // 3) output projection (split-K + atomics over bias-initialized Y)
    k_out_init<<<(B_ * DOUT) / 256, 256>>>(b_h2y, y);
    k_out<<<dim3(DOUT / 32, B_ / 32, 8), 128>>>(W_h2y, y);
}

// round 10
// speedup vs baseline: 5.7180x; 1.0019x over previous
#include <cuda_runtime.h>
#include <cuda_bf16.h>
#include <cstdint>
#include <cstddef>

#define B_   64
#define T_   512
#define DIN  1024
#define DH   2048
#define DOUT 1024
#define M1   (B_ * T_)   // 32768

// Recurrence persistent kernel: 128 blocks = 16 ntiles(128 col) x 8 kchunks(256 K)
#define NBLK    128
#define NTHR    256      // 8 warps: (kh, mh, nh)
#define KGG     128      // k16-groups over DH
#define WTILE_U4 8192    // W tile uint4s per block (128KB)

// ---------------------------------------------------------------------------
// Device globals (allocation-free scratch)
// ---------------------------------------------------------------------------
__device__ float    g_xh[(size_t)M1 * DH];        // 256 MB input projection (fp32)
__device__ float    g_h[B_ * DH];                 // final hidden state (fp32)
// W_h2h bf16 hi/lo packed in m16n8k16 B-fragment order, per block tile:
// uint4 {b0_hi, b1_hi, b0_lo, b1_lo} per (block, kg, nfl, lane)
__device__ uint4    g_Wf[(size_t)NBLK * WTILE_U4];   // 16 MB
// h bf16 hi/lo packed in A-fragment order:
// uint4 {a0,a1,a2,a3} per (kgg, mf, plane, lane)
__device__ uint4    g_hf[KGG * 4 * 2 * 32];          // 512 KB
__device__ float    g_part[16][B_][DH];              // split-K partials, 8 MB
__device__ unsigned g_bar_count;
__device__ unsigned g_bar_phase;

__device__ __forceinline__ float2 ffma2(float2 a, float2 b, float2 c) {
    float2 d;
    asm("fma.rn.f32x2 %0, %1, %2, %3;"
        : "=l"(reinterpret_cast<unsigned long long&>(d))
        : "l"(reinterpret_cast<unsigned long long&>(a)),
          "l"(reinterpret_cast<unsigned long long&>(b)),
          "l"(reinterpret_cast<unsigned long long&>(c)));
    return d;
}

// split (v0, v1) into bf16 hi plane + bf16 lo (residual) plane, packed bf16x2
__device__ __forceinline__ void split2(float v0, float v1,
                                       unsigned& hi, unsigned& lo) {
    __nv_bfloat162 h2 = __floats2bfloat162_rn(v0, v1);
    float2 hf = __bfloat1622float2(h2);
    __nv_bfloat162 l2 = __floats2bfloat162_rn(v0 - hf.x, v1 - hf.y);
    hi = *reinterpret_cast<unsigned*>(&h2);
    lo = *reinterpret_cast<unsigned*>(&l2);
}

__device__ __forceinline__ void mma_bf16(float* c, const uint4& a,
                                         unsigned b0, unsigned b1) {
    asm volatile(
        "mma.sync.aligned.m16n8k16.row.col.f32.bf16.bf16.f32 "
        "{%0,%1,%2,%3}, {%4,%5,%6,%7}, {%8,%9}, {%0,%1,%2,%3};"
        : "+f"(c[0]), "+f"(c[1]), "+f"(c[2]), "+f"(c[3])
        : "r"(a.x), "r"(a.y), "r"(a.z), "r"(a.w), "r"(b0), "r"(b1));
}

// ---------------------------------------------------------------------------
// Kernel 1 (NEW): g_xh = x @ W_x2h^T + b_x2h via bf16x3 tensor-core MMA.
// 128x128 tile, Kc=32 double-buffered fragment-order SMEM, 8 warps (4m x 2n).
// ---------------------------------------------------------------------------
__global__ __launch_bounds__(256) void k_xh_tc(const float* __restrict__ A,
                                               const float* __restrict__ W,
                                               const float* __restrict__ bias) {
    extern __shared__ uint4 smem[];
    uint4* sA = smem;          // [buf][kg][mf 0..7][plane 0..1][lane] : 2048 uint4
    uint4* sB = smem + 2048;   // [buf][kg][nfl 0..15][lane]          : 2048 uint4

    const int tid  = threadIdx.x;
    const int warp = tid >> 5;
    const int lane = tid & 31;
    const int wm = warp >> 1;      // 0..3 : rows wm*32..+31
    const int wn = warp & 1;       // 0..1 : cols wn*64..+63
    const int m0 = blockIdx.y * 128;
    const int n0 = blockIdx.x * 128;
    const int lr = lane >> 2;      // 0..7
    const int lk = (lane & 3) * 2;

    // loader base pointers (thread owns: A item (mf=warp, lane), kg 0/1;
    //                                  W items (nfl=warp, warp+8, lane), kg 0/1)
    const float* Ab = A + (size_t)(m0 + warp * 16 + lr) * DIN + lk;
    const float* Wb0 = W + (size_t)(n0 + warp * 8 + lr) * DIN + lk;
    const float* Wb1 = W + (size_t)(n0 + (warp + 8) * 8 + lr) * DIN + lk;

    float acc[2][8][4];
#pragma unroll
    for (int mi = 0; mi < 2; mi++)
#pragma unroll
        for (int nf = 0; nf < 8; nf++)
#pragma unroll
            for (int i = 0; i < 4; i++) acc[mi][nf][i] = 0.f;

    float2 ax[2][4];        // [kg][{(r,k),(r+8,k),(r,k+8),(r+8,k+8)}]
    float2 wx[2][2][2];     // [kg][nfl half][k01 / k89]

    auto gload = [&](int kc) {
#pragma unroll
        for (int kg = 0; kg < 2; kg++) {
            const float* ap = Ab + kc + kg * 16;
            ax[kg][0] = __ldg((const float2*)ap);
            ax[kg][1] = __ldg((const float2*)(ap + 8 * DIN));
            ax[kg][2] = __ldg((const float2*)(ap + 8));
            ax[kg][3] = __ldg((const float2*)(ap + 8 * DIN + 8));
            const float* wp0 = Wb0 + kc + kg * 16;
            const float* wp1 = Wb1 + kc + kg * 16;
            wx[kg][0][0] = __ldg((const float2*)wp0);
            wx[kg][0][1] = __ldg((const float2*)(wp0 + 8));
            wx[kg][1][0] = __ldg((const float2*)wp1);
            wx[kg][1][1] = __ldg((const float2*)(wp1 + 8));
        }
    };

    auto sstore = [&](int buf) {
#pragma unroll
        for (int kg = 0; kg < 2; kg++) {
            uint4 hi, lo;
            split2(ax[kg][0].x, ax[kg][0].y, hi.x, lo.x);
            split2(ax[kg][1].x, ax[kg][1].y, hi.y, lo.y);
            split2(ax[kg][2].x, ax[kg][2].y, hi.z, lo.z);
            split2(ax[kg][3].x, ax[kg][3].y, hi.w, lo.w);
            sA[buf * 1024 + kg * 512 + warp * 64 + lane]      = hi;
            sA[buf * 1024 + kg * 512 + warp * 64 + 32 + lane] = lo;
            uint4 v0, v1;
            split2(wx[kg][0][0].x, wx[kg][0][0].y, v0.x, v0.z);
            split2(wx[kg][0][1].x, wx[kg][0][1].y, v0.y, v0.w);
            split2(wx[kg][1][0].x, wx[kg][1][0].y, v1.x, v1.z);
            split2(wx[kg][1][1].x, wx[kg][1][1].y, v1.y, v1.w);
            sB[buf * 1024 + kg * 512 + warp * 32 + lane]       = v0;
            sB[buf * 1024 + kg * 512 + (warp + 8) * 32 + lane] = v1;
        }
    };

    auto compute = [&](int buf) {
#pragma unroll
        for (int kg = 0; kg < 2; kg++) {
            const int ab = buf * 1024 + kg * 512;
            uint4 Ah0 = sA[ab + (wm * 2) * 64 + lane];
            uint4 Al0 = sA[ab + (wm * 2) * 64 + 32 + lane];
            uint4 Ah1 = sA[ab + (wm * 2 + 1) * 64 + lane];
            uint4 Al1 = sA[ab + (wm * 2 + 1) * 64 + 32 + lane];
#pragma unroll
            for (int nf = 0; nf < 8; nf++) {
                uint4 w = sB[ab + (wn * 8 + nf) * 32 + lane];
                mma_bf16(acc[0][nf], Ah0, w.x, w.y);   // hi*hi
                mma_bf16(acc[0][nf], Al0, w.x, w.y);   // lo*hi
                mma_bf16(acc[0][nf], Ah0, w.z, w.w);   // hi*lo
                mma_bf16(acc[1][nf], Ah1, w.x, w.y);
                mma_bf16(acc[1][nf], Al1, w.x, w.y);
                mma_bf16(acc[1][nf], Ah1, w.z, w.w);
            }
        }
    };

    gload(0);
    sstore(0);
    __syncthreads();

    for (int kc = 0; kc < DIN; kc += 32) {
        const int buf = (kc >> 5) & 1;
        const bool more = (kc + 32) < DIN;
        if (more) gload(kc + 32);
        compute(buf);
        if (more) sstore(buf ^ 1);
        __syncthreads();
    }

    // epilogue: add bias, store fp32
#pragma unroll
    for (int nf = 0; nf < 8; nf++) {
        const int c = n0 + wn * 64 + nf * 8 + lk;
        float2 bb = __ldg((const float2*)(bias + c));
#pragma unroll
        for (int mi = 0; mi < 2; mi++) {
            const int r = m0 + wm * 32 + mi * 16 + lr;
            *(float2*)(g_xh + (size_t)r * DH + c) =
                make_float2(acc[mi][nf][0] + bb.x, acc[mi][nf][1] + bb.y);
            *(float2*)(g_xh + (size_t)(r + 8) * DH + c) =
                make_float2(acc[mi][nf][2] + bb.x, acc[mi][nf][3] + bb.y);
        }
    }
}

// ---------------------------------------------------------------------------
// Pack W_h2h into bf16 hi/lo B-fragment order (per-block 128KB tiles).
// ---------------------------------------------------------------------------
__global__ void k_packw(const float* __restrict__ W) {
    size_t u = (size_t)blockIdx.x * 256 + threadIdx.x;   // 0 .. 1M-1
    int b    = (int)(u >> 13);
    int r    = (int)(u & 8191);
    int kg   = r >> 9;          // 0..15
    int nfl  = (r >> 5) & 15;   // 0..15
    int lane = r & 31;
    int nt = b >> 3, kch = b & 7;
    int n = nt * 128 + nfl * 8 + (lane >> 2);
    int k = kch * 256 + kg * 16 + (lane & 3) * 2;
    const float* row = W + (size_t)n * DH;
    float w0 = row[k],     w1 = row[k + 1];
    float w2 = row[k + 8], w3 = row[k + 9];
    uint4 v;
    unsigned lo01, lo89;
    split2(w0, w1, v.x, lo01);
    split2(w2, w3, v.y, lo89);
    v.z = lo01;
    v.w = lo89;
    g_Wf[u] = v;
}

// ---------------------------------------------------------------------------
// Persistent recurrence kernel: bf16x3 mma.m16n8k16, W tile persistent in SMEM,
// 8 warps (2/SMSP), A fragments L2-direct, 16-way split-K partials.
// xh loads for the epilogue are hoisted above the MMA phase (DRAM latency hide).
// ---------------------------------------------------------------------------
__global__ __launch_bounds__(NTHR, 1) void k_recur() {
    extern __shared__ uint4 sW[];   // 8192 uint4 = 128 KB

    const int tid  = threadIdx.x;
    const int b    = blockIdx.x;
    const int warp = tid >> 5;
    const int lane = tid & 31;
    const int kh = warp >> 2;          // k-half (0/1): 128 K each
    const int mh = (warp >> 1) & 1;    // m-half: rows mh*32..+31
    const int nh = warp & 1;           // n-half: cols nh*64..+63
    const int nt  = b >> 3;            // ntile 0..15
    const int kch = b & 7;             // kchunk 0..7
    const int pk  = kch * 2 + kh;      // partial buffer index

    // Load persistent W tile into SMEM (once)
    {
        const uint4* wsrc = g_Wf + (size_t)b * WTILE_U4;
        for (int i = tid; i < WTILE_U4; i += NTHR) sW[i] = __ldg(wsrc + i);
    }

    // replay-safe grid barrier
    unsigned bar_base;
    asm volatile("ld.acquire.gpu.global.u32 %0, [%1];"
                 : "=r"(bar_base) : "l"(&g_bar_phase));
    unsigned bar_t = 0;

    auto grid_bar = [&]() {
        bar_t++;
        __syncthreads();
        __threadfence();
        if (tid == 0) {
            unsigned arr = atomicAdd(&g_bar_count, 1);
            if (arr == NBLK - 1) {
                atomicExch(&g_bar_count, 0);
                __threadfence();
                atomicAdd(&g_bar_phase, 1);
            } else {
                unsigned p;
                do {
                    __nanosleep(32);
                    asm volatile("ld.acquire.gpu.global.u32 %0, [%1];"
                                 : "=r"(p) : "l"(&g_bar_phase));
                } while (p - bar_base < bar_t);
            }
        }
        __syncthreads();
    };

    // Epilogue mapping: block b owns kgg = b (16 h-columns), threads 0..127
    const int elane = tid & 31;
    const int emf   = (tid >> 5) & 3;
    const int er    = emf * 16 + (elane >> 2);       // row (and +8)
    const int ek0   = b * 16 + (elane & 3) * 2;      // col (and +1, +8, +9)
    uint4* hf_hi = g_hf + ((b * 4 + emf) * 2 + 0) * 32 + elane;
    uint4* hf_lo = g_hf + ((b * 4 + emf) * 2 + 1) * 32 + elane;

    // preloaded xh values for epilogue of step s (loads xh_{s-1})
    auto xh_load = [&](int s, float2& v00, float2& v01, float2& v10, float2& v11) {
        const float* x0 = &g_xh[((size_t)er * T_ + (s - 1)) * DH + ek0];
        const float* x1 = &g_xh[((size_t)(er + 8) * T_ + (s - 1)) * DH + ek0];
        v00 = __ldg((const float2*)x0);
        v01 = __ldg((const float2*)(x0 + 8));
        v10 = __ldg((const float2*)x1);
        v11 = __ldg((const float2*)(x1 + 8));
    };

    auto epilogue = [&](int s, float2 v00, float2 v01, float2 v10, float2 v11,
                        bool addp) {
        if (addp) {
#pragma unroll
            for (int p = 0; p < 16; p++) {
                const float* pb = &g_part[p][0][0];
                const float* p0 = pb + (size_t)er * DH + ek0;
                const float* p1 = pb + (size_t)(er + 8) * DH + ek0;
                float2 q;
                q = __ldcg((const float2*)p0);       v00.x += q.x; v00.y += q.y;
                q = __ldcg((const float2*)(p0 + 8)); v01.x += q.x; v01.y += q.y;
                q = __ldcg((const float2*)p1);       v10.x += q.x; v10.y += q.y;
                q = __ldcg((const float2*)(p1 + 8)); v11.x += q.x; v11.y += q.y;
            }
        }
        v00.x = fmaxf(v00.x, 0.f); v00.y = fmaxf(v00.y, 0.f);
        v01.x = fmaxf(v01.x, 0.f); v01.y = fmaxf(v01.y, 0.f);
        v10.x = fmaxf(v10.x, 0.f); v10.y = fmaxf(v10.y, 0.f);
        v11.x = fmaxf(v11.x, 0.f); v11.y = fmaxf(v11.y, 0.f);
        uint4 hi, lo;
        split2(v00.x, v00.y, hi.x, lo.x);   // a0: (r,   k0,k0+1)
        split2(v10.x, v10.y, hi.y, lo.y);   // a1: (r+8, k0,k0+1)
        split2(v01.x, v01.y, hi.z, lo.z);   // a2: (r,   k0+8,k0+9)
        split2(v11.x, v11.y, hi.w, lo.w);   // a3: (r+8, k0+8,k0+9)
        *hf_hi = hi;
        *hf_lo = lo;
        if (s == T_) {
            *(float2*)&g_h[(size_t)er * DH + ek0]           = v00;
            *(float2*)&g_h[(size_t)er * DH + ek0 + 8]       = v01;
            *(float2*)&g_h[(size_t)(er + 8) * DH + ek0]     = v10;
            *(float2*)&g_h[(size_t)(er + 8) * DH + ek0 + 8] = v11;
        }
    };

    if (tid < 128) {   // h_1 = relu(xh_0)
        float2 v00, v01, v10, v11;
        xh_load(1, v00, v01, v10, v11);
        epilogue(1, v00, v01, v10, v11, false);
    }
    grid_bar();

    const int kggbase = kch * 16 + kh * 8;

    for (int s = 2; s <= T_; s++) {
        // hoisted epilogue xh loads for this step (hide DRAM latency under MMA)
        float2 pv00, pv01, pv10, pv11;
        if (tid < 128) xh_load(s, pv00, pv01, pv10, pv11);

        // ---- MMA phase: partial[pk] = h_{s-1}[:, kslice] @ W[ntile, kslice]^T
        float acc[2][8][4];
#pragma unroll
        for (int mi = 0; mi < 2; mi++)
#pragma unroll
            for (int nf = 0; nf < 8; nf++)
#pragma unroll
                for (int i = 0; i < 4; i++) acc[mi][nf][i] = 0.f;

        // prefetch kg=0 A fragments
        const uint4* ab0 = g_hf + ((kggbase * 4 + mh * 2) * 2) * 32 + lane;
        uint4 A0h = __ldcg(ab0);
        uint4 A0l = __ldcg(ab0 + 32);
        uint4 A1h = __ldcg(ab0 + 64);
        uint4 A1l = __ldcg(ab0 + 96);

#pragma unroll
        for (int kg = 0; kg < 8; kg++) {
            uint4 N0h, N0l, N1h, N1l;
            if (kg < 7) {
                const uint4* ab =
                    g_hf + (((kggbase + kg + 1) * 4 + mh * 2) * 2) * 32 + lane;
                N0h = __ldcg(ab);
                N0l = __ldcg(ab + 32);
                N1h = __ldcg(ab + 64);
                N1l = __ldcg(ab + 96);
            }
            const int wb = ((kh * 8 + kg) * 16 + nh * 8) * 32 + lane;
#pragma unroll
            for (int nf = 0; nf < 8; nf++) {
                uint4 w = sW[wb + nf * 32];
                mma_bf16(acc[0][nf], A0h, w.x, w.y);   // hi*hi
                mma_bf16(acc[0][nf], A0l, w.x, w.y);   // lo*hi
                mma_bf16(acc[0][nf], A0h, w.z, w.w);   // hi*lo
                mma_bf16(acc[1][nf], A1h, w.x, w.y);
                mma_bf16(acc[1][nf], A1l, w.x, w.y);
                mma_bf16(acc[1][nf], A1h, w.z, w.w);
            }
            if (kg < 7) { A0h = N0h; A0l = N0l; A1h = N1h; A1l = N1l; }
        }

        // write split-K partials (fp32)
        {
            float* pb = &g_part[pk][0][0];
            const int cb = nt * 128 + nh * 64 + (lane & 3) * 2;
#pragma unroll
            for (int mi = 0; mi < 2; mi++) {
                const int r = mh * 32 + mi * 16 + (lane >> 2);
#pragma unroll
                for (int nf = 0; nf < 8; nf++) {
                    const int c = cb + nf * 8;
                    *(float2*)&pb[(size_t)r * DH + c] =
                        make_float2(acc[mi][nf][0], acc[mi][nf][1]);
                    *(float2*)&pb[(size_t)(r + 8) * DH + c] =
                        make_float2(acc[mi][nf][2], acc[mi][nf][3]);
                }
            }
        }
        grid_bar();

        if (tid < 128) epilogue(s, pv00, pv01, pv10, pv11, true);
        grid_bar();
    }
}

// ---------------------------------------------------------------------------
// Kernel 3: y = g_h @ W_h2y^T + b_h2y, 8-way split-K + atomicAdd.
// ---------------------------------------------------------------------------
__global__ void k_out_init(const float* __restrict__ bias, float* __restrict__ Y) {
    int idx = blockIdx.x * 256 + threadIdx.x;
    Y[idx] = bias[idx & (DOUT - 1)];
}

__global__ __launch_bounds__(128) void k_out(const float* __restrict__ W,
                                             float* __restrict__ Y) {
    __shared__ float Hs[16][32];
    __shared__ float Ws[16][32];
    const int n0  = blockIdx.x * 32;
    const int m0  = blockIdx.y * 32;
    const int kc0 = blockIdx.z * (DH / 8);
    const int t   = threadIdx.x;
    const int nx = t & 15, my = t >> 4;
    const float* __restrict__ Hin = g_h;
    const int lrow = t >> 2;
    const int lkq  = t & 3;

    float2 acc[2][2] = { { make_float2(0.f, 0.f), make_float2(0.f, 0.f) },
                         { make_float2(0.f, 0.f), make_float2(0.f, 0.f) } };

    for (int k0 = kc0; k0 < kc0 + DH / 8; k0 += 16) {
        float4 va = *(const float4*)(Hin + (size_t)(m0 + lrow) * DH + k0 + lkq * 4);
        float4 vb = *(const float4*)(W   + (size_t)(n0 + lrow) * DH + k0 + lkq * 4);
        __syncthreads();
        Hs[lkq*4+0][lrow] = va.x; Hs[lkq*4+1][lrow] = va.y;
        Hs[lkq*4+2][lrow] = va.z; Hs[lkq*4+3][lrow] = va.w;
        Ws[lkq*4+0][lrow] = vb.x; Ws[lkq*4+1][lrow] = vb.y;
        Ws[lkq*4+2][lrow] = vb.z; Ws[lkq*4+3][lrow] = vb.w;
        __syncthreads();

#pragma unroll
        for (int kk = 0; kk < 16; kk++) {
            float4 a = *(const float4*)&Hs[kk][my*4];
            float2 bq = *(const float2*)&Ws[kk][nx*2];
            float2 ap0 = make_float2(a.x, a.y), ap1 = make_float2(a.z, a.w);
            float2 b0  = make_float2(bq.x, bq.x), b1  = make_float2(bq.y, bq.y);
            acc[0][0] = ffma2(ap0, b0, acc[0][0]);
            acc[1][0] = ffma2(ap1, b0, acc[1][0]);
            acc[0][1] = ffma2(ap0, b1, acc[0][1]);
            acc[1][1] = ffma2(ap1, b1, acc[1][1]);
        }
    }

    const int c0 = n0 + nx*2;
#pragma unroll
    for (int i = 0; i < 4; i++) {
        int m = m0 + my*4 + i;
        float v0 = (i & 1) ? acc[i>>1][0].y : acc[i>>1][0].x;
        float v1 = (i & 1) ? acc[i>>1][1].y : acc[i>>1][1].x;
        atomicAdd(&Y[(size_t)m * DOUT + c0],     v0);
        atomicAdd(&Y[(size_t)m * DOUT + c0 + 1], v1);
    }
}

// ---------------------------------------------------------------------------
extern "C" void kernel_launch(void* const* d_in, const int* in_sizes, int n_in,
                              void* d_out, int out_size) {
    (void)in_sizes; (void)n_in; (void)out_size;
    const float* x     = (const float*)d_in[0];
    const float* W_x2h = (const float*)d_in[1];
    const float* b_x2h = (const float*)d_in[2];
    const float* W_h2h = (const float*)d_in[3];
    const float* W_h2y = (const float*)d_in[4];
    const float* b_h2y = (const float*)d_in[5];
    float* y = (float*)d_out;

    cudaFuncSetAttribute(k_recur, cudaFuncAttributeMaxDynamicSharedMemorySize,
                         WTILE_U4 * sizeof(uint4));
    cudaFuncSetAttribute(k_xh_tc, cudaFuncAttributeMaxDynamicSharedMemorySize,
                         65536);

    // 1) input projection (bf16x3 tensor cores) + W bf16 hi/lo fragment pack
    k_xh_tc<<<dim3(DH / 128, M1 / 128), 256, 65536>>>(x, W_x2h, b_x2h);
    k_packw<<<(NBLK * WTILE_U4) / 256, 256>>>(W_h2h);

    // 2) all 512 recurrence steps in ONE persistent kernel (bf16x3 MMA,
    //    W-in-SMEM persistent, L2-direct A fragments, 16-way split-K)
    k_recur<<<NBLK, NTHR, WTILE_U4 * sizeof(uint4)>>>();

    // 3) output projection (split-K + atomics over bias-initialized Y)
    k_out_init<<<(B_ * DOUT) / 256, 256>>>(b_h2y, y);
    k_out<<<dim3(DOUT / 32, B_ / 32, 8), 128>>>(W_h2y, y);
}